// round 7
// baseline (speedup 1.0000x reference)
#include <cuda_runtime.h>
#include <cuda_fp16.h>
#include <cstdint>

#define TT 8
#define HH 64
#define WWD 64
#define HWX 4096
#define PLANE 32768
#define KTAP 27

// -------- device scratch --------
__device__ __half g_xh[64*PLANE];        // x fp16, [pos][c]
__device__ __half g_y1h[64*PLANE];       // lrelu(conv1) fp16, [pos][c]
__device__ float  g_off[54*PLANE];       // offsets fp32, [o][pos]
__device__ __half g_W1h[KTAP*64*64];     // [tap][o][c]
__device__ __half g_Woffh[KTAP*64*64];
__device__ __half g_Wdh[KTAP*64*64];
__device__ __half g_Wrh[64*64];          // [o][c]

__device__ __forceinline__ uint32_t smem_u32(const void* p){
    uint32_t a;
    asm("{ .reg .u64 t; cvta.to.shared.u64 t, %1; cvt.u32.u64 %0, t; }"
        : "=r"(a) : "l"(p));
    return a;
}
__device__ __forceinline__ void ldsm4(uint32_t& r0,uint32_t& r1,uint32_t& r2,uint32_t& r3, uint32_t addr){
    asm volatile("ldmatrix.sync.aligned.m8n8.x4.shared.b16 {%0,%1,%2,%3}, [%4];"
        : "=r"(r0),"=r"(r1),"=r"(r2),"=r"(r3) : "r"(addr));
}
__device__ __forceinline__ void mma16816(float* d, uint32_t a0,uint32_t a1,uint32_t a2,uint32_t a3,
                                         uint32_t b0,uint32_t b1){
    asm volatile("mma.sync.aligned.m16n8k16.row.col.f32.f16.f16.f32 "
        "{%0,%1,%2,%3},{%4,%5,%6,%7},{%8,%9},{%0,%1,%2,%3};"
        : "+f"(d[0]),"+f"(d[1]),"+f"(d[2]),"+f"(d[3])
        : "r"(a0),"r"(a1),"r"(a2),"r"(a3),"r"(b0),"r"(b1));
}

// half (2 of 4 k16-stages) of one K=64 chunk: A[64pos x 64k] x B[64ch x 64k]^T
// warp tile: m16 (pos, at m0) x n32 (ch, at n0)
template<int ST0>
__device__ __forceinline__ void gemm_half(uint32_t Ab, uint32_t Bb, int m0, int n0,
                                          int lane, float acc[4][4]){
    int g = lane>>3, r = lane&7;
    #pragma unroll
    for (int s=0;s<2;s++){
        int st = ST0 + s;
        int rowA = m0 + (g&1)*8 + r;
        int segA = st*2 + (g>>1);
        uint32_t a0,a1,a2,a3;
        ldsm4(a0,a1,a2,a3, Ab + rowA*128 + ((segA ^ (rowA&7))<<4));
        #pragma unroll
        for (int p=0;p<2;p++){
            int rowB = n0 + p*16 + (g>>1)*8 + r;
            int segB = st*2 + (g&1);
            uint32_t b0,b1,b2,b3;
            ldsm4(b0,b1,b2,b3, Bb + rowB*128 + ((segB ^ (rowB&7))<<4));
            mma16816(acc[2*p],   a0,a1,a2,a3, b0,b1);
            mma16816(acc[2*p+1], a0,a1,a2,a3, b2,b3);
        }
    }
}

__device__ __forceinline__ uint4 bilin8(const uint4* P, const float* W){
    uint4 r;
    const uint32_t* p0 = (const uint32_t*)&P[0];
    const uint32_t* p1 = (const uint32_t*)&P[1];
    const uint32_t* p2 = (const uint32_t*)&P[2];
    const uint32_t* p3 = (const uint32_t*)&P[3];
    uint32_t* ro = (uint32_t*)&r;
    #pragma unroll
    for (int k=0;k<4;k++){
        float2 f0 = __half22float2(*(const __half2*)&p0[k]);
        float2 f1 = __half22float2(*(const __half2*)&p1[k]);
        float2 f2 = __half22float2(*(const __half2*)&p2[k]);
        float2 f3 = __half22float2(*(const __half2*)&p3[k]);
        float vx = W[0]*f0.x + W[1]*f1.x + W[2]*f2.x + W[3]*f3.x;
        float vy = W[0]*f0.y + W[1]*f1.y + W[2]*f2.y + W[3]*f3.y;
        __half2 h = __floats2half2_rn(vx, vy);
        ro[k] = *(uint32_t*)&h;
    }
    return r;
}

// -------- prep --------
__global__ void prep_weights(const float* __restrict__ W1, const float* __restrict__ Woff,
                             const float* __restrict__ Wd, const float* __restrict__ Wr){
    int i = blockIdx.x*256 + threadIdx.x;
    if (i < KTAP*64*64){
        int tap = i>>12, o = (i>>6)&63, c = i&63;
        int src = o*1728 + c*27 + tap;
        g_W1h[i] = __float2half(W1[src]);
        g_Wdh[i] = __float2half(Wd[src]);
        g_Woffh[i] = (o < 54) ? __float2half(Woff[src]) : __half(0.f);
        if (i < 64*64) g_Wrh[i] = __float2half(Wr[i]);
    }
}

__global__ void prep_x(const float* __restrict__ x){
    __shared__ __half sT[128*72];
    int tid = threadIdx.x;
    int pos0 = blockIdx.x*128;
    int p = tid & 127, ch0 = tid >> 7;
    #pragma unroll 8
    for (int cc = 0; cc < 32; cc++){
        int c = cc*2 + ch0;
        sT[p*72 + c] = __float2half(x[c*PLANE + pos0 + p]);
    }
    __syncthreads();
    int oc = tid & 7;
    #pragma unroll
    for (int j = 0; j < 4; j++){
        int n = (tid>>3) + j*32;
        uint4 v = *(uint4*)&sT[n*72 + oc*8];
        *(uint4*)&g_xh[(pos0+n)*64 + oc*8] = v;
    }
}

// ==================== conv 3x3x3, N=64, pipelined ====================
// smem: misc[0,1024) | SA0@1024 SA1@9216 SB0@17408 SB1@25600 (8KB each), end 33792
// epilogue aliases @1024
#define SMEM_CONV 33792
template<int MODE>   // 0: xh -> y1h (lrelu); 1: y1h -> g_off (54 ch)
__global__ void __launch_bounds__(256)
conv_f16(const float* __restrict__ bias)
{
    extern __shared__ char sm[];
    float* sBias = (float*)sm;
    char* SA0 = sm + 1024;
    char* SA1 = sm + 9216;
    char* SB0 = sm + 17408;
    char* SB1 = sm + 25600;
    uint32_t sbase = smem_u32(sm);
    const __half* src  = (MODE==0)? g_xh  : g_y1h;
    const __half* Wall = (MODE==0)? g_W1h : g_Woffh;

    int tid = threadIdx.x, lane = tid&31, wid = tid>>5;
    int t = blockIdx.x>>6, h = blockIdx.x&63;
    if (tid < 64) sBias[tid] = (MODE==0 || tid<54)? bias[tid] : 0.f;

    int oc = tid&7;
    int o_w = tid>>2, part = tid&3, s0w = part*2;
    int m0 = (wid&3)*16, n0 = (wid>>2)*32;
    float acc[4][4];
    #pragma unroll
    for (int i=0;i<4;i++){ acc[i][0]=0.f; acc[i][1]=0.f; acc[i][2]=0.f; acc[i][3]=0.f; }

    // ---- prefetch helpers (inline lambdas via macros) ----
    uint4 Av[2], Bv0, Bv1;
    #define CONV_LDG(tap) do{ \
        int kt=(tap)/9, rr=(tap)-kt*9, kh=rr/3, kw=rr-kh*3; \
        int t_in = t-1+kt, h_in = h-1+kh; \
        _Pragma("unroll") \
        for (int jj=0;jj<2;jj++){ \
            int n = (tid>>3) + jj*32; \
            int w_in = n-1+kw; \
            bool valid = ((unsigned)t_in<TT)&&((unsigned)h_in<HH)&&((unsigned)w_in<WWD); \
            Av[jj] = make_uint4(0,0,0,0); \
            if (valid) Av[jj] = *(const uint4*)&src[(t_in*HWX + h_in*WWD + w_in)*64 + oc*8]; \
        } \
        const uint4* sp = (const uint4*)(Wall + (tap)*4096 + o_w*64 + part*16); \
        Bv0 = sp[0]; Bv1 = sp[1]; \
    } while(0)
    #define CONV_STS(SA, SB) do{ \
        _Pragma("unroll") \
        for (int jj=0;jj<2;jj++){ \
            int n = (tid>>3) + jj*32; \
            *(uint4*)((SA) + n*128 + ((oc ^ (n&7))<<4)) = Av[jj]; \
        } \
        *(uint4*)((SB) + o_w*128 + ((s0w ^ (o_w&7))<<4)) = Bv0; \
        *(uint4*)((SB) + o_w*128 + (((s0w+1)^(o_w&7))<<4)) = Bv1; \
    } while(0)

    CONV_LDG(0);
    CONV_STS(SA0, SB0);
    __syncthreads();

    for (int tap=0; tap<KTAP; tap++){
        int p = tap&1;
        uint32_t Ab = sbase + (p ? 9216 : 1024);
        uint32_t Bb = sbase + (p ? 25600 : 17408);
        bool more = (tap+1) < KTAP;
        if (more) CONV_LDG(tap+1);
        gemm_half<0>(Ab,Bb,m0,n0,lane,acc);
        gemm_half<2>(Ab,Bb,m0,n0,lane,acc);
        if (more){
            char* SAn = p ? SA0 : SA1;
            char* SBn = p ? SB0 : SB1;
            CONV_STS(SAn, SBn);
        }
        __syncthreads();
    }

    int q = lane>>2, c2 = (lane&3)<<1;
    int base = t*HWX + h*WWD;
    if (MODE==0){
        uint32_t* sOutH2 = (uint32_t*)(sm + 1024);  // [pos][36] half2
        #pragma unroll
        for (int nt=0;nt<4;nt++){
            int o = n0 + nt*8 + c2;
            float b0v = sBias[o], b1v = sBias[o+1];
            float v0 = acc[nt][0]+b0v, v1 = acc[nt][1]+b1v;
            float v2 = acc[nt][2]+b0v, v3 = acc[nt][3]+b1v;
            v0 = v0>=0.f?v0:0.01f*v0; v1 = v1>=0.f?v1:0.01f*v1;
            v2 = v2>=0.f?v2:0.01f*v2; v3 = v3>=0.f?v3:0.01f*v3;
            __half2 h01 = __floats2half2_rn(v0,v1);
            __half2 h23 = __floats2half2_rn(v2,v3);
            sOutH2[(m0+q)*36   + (o>>1)] = *(uint32_t*)&h01;
            sOutH2[(m0+q+8)*36 + (o>>1)] = *(uint32_t*)&h23;
        }
        __syncthreads();
        __half* sOutH = (__half*)(sm + 1024);
        #pragma unroll
        for (int jj=0;jj<2;jj++){
            int n = (tid>>3) + jj*32;
            uint4 v = *(uint4*)&sOutH[n*72 + oc*8];
            *(uint4*)&g_y1h[(base+n)*64 + oc*8] = v;
        }
    } else {
        float* sOut = (float*)(sm + 1024);   // [o][68]
        #pragma unroll
        for (int nt=0;nt<4;nt++){
            int o = n0 + nt*8 + c2;
            float b0v = sBias[o], b1v = sBias[o+1];
            sOut[o*68 + m0+q]       = acc[nt][0]+b0v;
            sOut[(o+1)*68 + m0+q]   = acc[nt][1]+b1v;
            sOut[o*68 + m0+q+8]     = acc[nt][2]+b0v;
            sOut[(o+1)*68 + m0+q+8] = acc[nt][3]+b1v;
        }
        __syncthreads();
        int o = tid>>2;
        if (o < 54){
            #pragma unroll
            for (int k=0;k<4;k++){
                int nn = (tid&3)*16 + k*4;
                float4 v = *(float4*)&sOut[o*68 + nn];
                *(float4*)&g_off[o*PLANE + base + nn] = v;
            }
        }
    }
    #undef CONV_LDG
    #undef CONV_STS
}

// ==================== deformable conv + residual + lrelu, N=64, pipelined ====================
// smem: misc[0,1024) | SA0@1024 SA1@9216 SB0@17408 SB1@25600 | tab@33792 (13824) end 47616
// epilogue fp32 [o][68] aliases @1024
#define SMEM_DEF 47616
__global__ void __launch_bounds__(256)
deform_f16(const float* __restrict__ bd, const float* __restrict__ br,
           float* __restrict__ out)
{
    extern __shared__ char sm[];
    float* sBd = (float*)sm;
    float* sBr = (float*)(sm + 256);
    char* SA0 = sm + 1024;
    char* SA1 = sm + 9216;
    char* SB0 = sm + 17408;
    char* SB1 = sm + 25600;
    uint2* sTab = (uint2*)(sm + 33792);
    uint32_t sbase = smem_u32(sm);

    int tid = threadIdx.x, lane = tid&31, wid = tid>>5;
    int t = blockIdx.x>>6, h = blockIdx.x&63;
    if (tid < 64){ sBd[tid] = bd[tid]; sBr[tid] = br[tid]; }

    // bilinear tap table: 27*64 entries, 8B each
    for (int e = tid; e < KTAP*64; e += 256){
        int tap = e>>6, n = e&63;
        int kt = tap/9, rr = tap-kt*9, kh = rr/3, kw = rr-kh*3;
        int t_in = t-1+kt;
        bool t_ok = (unsigned)t_in < TT;
        int t_c = min(max(t_in,0),TT-1);
        int pidx = t*HWX + h*WWD + n;
        float dh = g_off[(2*tap)*PLANE + pidx];
        float dw = g_off[(2*tap+1)*PLANE + pidx];
        float h_s = (float)(h-1+kh)+dh, w_s = (float)(n-1+kw)+dw;
        float h0f = floorf(h_s), w0f = floorf(w_s);
        float fh = h_s-h0f, fw = w_s-w0f;
        int hb = (int)h0f, wb = (int)w0f;
        unsigned mask = 0;
        if (t_ok){
            unsigned h0ok = ((unsigned)hb < HH),  h1ok = ((unsigned)(hb+1) < HH);
            unsigned w0ok = ((unsigned)wb < WWD), w1ok = ((unsigned)(wb+1) < WWD);
            mask = (h0ok&w0ok) | ((h0ok&w1ok)<<1) | ((h1ok&w0ok)<<2) | ((h1ok&w1ok)<<3);
        }
        int hbc = min(max(hb,-2),64), wbc = min(max(wb,-2),64);
        uint32_t pack = (uint32_t)(wbc+2) | ((uint32_t)(hbc+2)<<7) | ((uint32_t)t_c<<14) | (mask<<17);
        __half2 f2 = __floats2half2_rn(fh, fw);
        sTab[e] = make_uint2(pack, *(uint32_t*)&f2);
    }
    __syncthreads();

    int oc = tid&7;
    int o_w = tid>>2, part = tid&3, s0w = part*2;
    int m0 = (wid&3)*16, n0 = (wid>>2)*32;
    int base_p = t*HWX + h*WWD;
    float acc[4][4];
    #pragma unroll
    for (int i=0;i<4;i++){ acc[i][0]=0.f; acc[i][1]=0.f; acc[i][2]=0.f; acc[i][3]=0.f; }

    uint4 P[2][4]; float W[2][4];
    uint4 Bv0, Bv1;
    #define DEF_LDG(it) do{ \
        if ((it) < KTAP){ \
            _Pragma("unroll") \
            for (int jj=0;jj<2;jj++){ \
                int n = (tid>>3) + jj*32; \
                uint2 tb = sTab[(it)*64 + n]; \
                uint32_t pk = tb.x; \
                __half2 fhw = *(__half2*)&tb.y; \
                float fh = __low2float(fhw), fw = __high2float(fhw); \
                int wb = (int)(pk&127)-2, hb = (int)((pk>>7)&127)-2; \
                int tc = (int)((pk>>14)&7); \
                unsigned mask = pk>>17; \
                float w00=(1.f-fh)*(1.f-fw), w01=(1.f-fh)*fw, w10=fh*(1.f-fw), w11=fh*fw; \
                if(!(mask&1u)) w00=0.f; \
                if(!(mask&2u)) w01=0.f; \
                if(!(mask&4u)) w10=0.f; \
                if(!(mask&8u)) w11=0.f; \
                int ih0=min(max(hb,0),HH-1),  ih1=min(max(hb+1,0),HH-1); \
                int iw0=min(max(wb,0),WWD-1), iw1=min(max(wb+1,0),WWD-1); \
                int b0i = tc*HWX; \
                P[jj][0] = *(const uint4*)&g_y1h[(b0i+ih0*WWD+iw0)*64 + oc*8]; \
                P[jj][1] = *(const uint4*)&g_y1h[(b0i+ih0*WWD+iw1)*64 + oc*8]; \
                P[jj][2] = *(const uint4*)&g_y1h[(b0i+ih1*WWD+iw0)*64 + oc*8]; \
                P[jj][3] = *(const uint4*)&g_y1h[(b0i+ih1*WWD+iw1)*64 + oc*8]; \
                W[jj][0]=w00; W[jj][1]=w01; W[jj][2]=w10; W[jj][3]=w11; \
            } \
            const uint4* sp = (const uint4*)(g_Wdh + (it)*4096 + o_w*64 + part*16); \
            Bv0 = sp[0]; Bv1 = sp[1]; \
        } else { \
            _Pragma("unroll") \
            for (int jj=0;jj<2;jj++){ \
                int n = (tid>>3) + jj*32; \
                P[jj][0] = *(const uint4*)&g_xh[(base_p+n)*64 + oc*8]; \
                P[jj][1] = make_uint4(0,0,0,0); \
                P[jj][2] = make_uint4(0,0,0,0); \
                P[jj][3] = make_uint4(0,0,0,0); \
                W[jj][0]=1.f; W[jj][1]=0.f; W[jj][2]=0.f; W[jj][3]=0.f; \
            } \
            const uint4* sp = (const uint4*)(g_Wrh + o_w*64 + part*16); \
            Bv0 = sp[0]; Bv1 = sp[1]; \
        } \
    } while(0)
    #define DEF_STS(SA, SB) do{ \
        _Pragma("unroll") \
        for (int jj=0;jj<2;jj++){ \
            int n = (tid>>3) + jj*32; \
            uint4 rv = bilin8(P[jj], W[jj]); \
            *(uint4*)((SA) + n*128 + ((oc ^ (n&7))<<4)) = rv; \
        } \
        *(uint4*)((SB) + o_w*128 + ((s0w ^ (o_w&7))<<4)) = Bv0; \
        *(uint4*)((SB) + o_w*128 + (((s0w+1)^(o_w&7))<<4)) = Bv1; \
    } while(0)

    DEF_LDG(0);
    DEF_STS(SA0, SB0);
    __syncthreads();

    int c2 = (lane&3)<<1, q = lane>>2;
    // 28 chunks: taps 0..26 + residual (27)
    for (int it = 0; it < 28; it++){
        int p = it & 1;
        uint32_t Ab = sbase + (p ? 9216 : 1024);
        uint32_t Bb = sbase + (p ? 25600 : 17408);
        bool more = (it+1) < 28;
        if (more) DEF_LDG(it+1);
        gemm_half<0>(Ab,Bb,m0,n0,lane,acc);
        gemm_half<2>(Ab,Bb,m0,n0,lane,acc);
        if (more){
            char* SAn = p ? SA0 : SA1;
            char* SBn = p ? SB0 : SB1;
            DEF_STS(SAn, SBn);
        }
        if (it == 26){
            // fold deform bias + lrelu before the residual chunk
            #pragma unroll
            for (int nt=0;nt<4;nt++){
                int o = n0 + nt*8 + c2;
                float b0v = sBd[o], b1v = sBd[o+1];
                float v;
                v = acc[nt][0]+b0v; acc[nt][0] = v>=0.f?v:0.01f*v;
                v = acc[nt][1]+b1v; acc[nt][1] = v>=0.f?v:0.01f*v;
                v = acc[nt][2]+b0v; acc[nt][2] = v>=0.f?v:0.01f*v;
                v = acc[nt][3]+b1v; acc[nt][3] = v>=0.f?v:0.01f*v;
            }
        }
        __syncthreads();
    }

    // epilogue: + br, transpose, coalesced stores
    float* sOut = (float*)(sm + 1024);  // [o][68]
    #pragma unroll
    for (int nt=0;nt<4;nt++){
        int o = n0 + nt*8 + c2;
        float b0v = sBr[o], b1v = sBr[o+1];
        sOut[o*68 + m0+q]       = acc[nt][0]+b0v;
        sOut[(o+1)*68 + m0+q]   = acc[nt][1]+b1v;
        sOut[o*68 + m0+q+8]     = acc[nt][2]+b0v;
        sOut[(o+1)*68 + m0+q+8] = acc[nt][3]+b1v;
    }
    __syncthreads();
    {
        int o = tid>>2;
        #pragma unroll
        for (int k=0;k<4;k++){
            int nn = (tid&3)*16 + k*4;
            float4 v = *(float4*)&sOut[o*68 + nn];
            *(float4*)&out[o*PLANE + base_p + nn] = v;
        }
    }
    #undef DEF_LDG
    #undef DEF_STS
}

// -------- launch --------
extern "C" void kernel_launch(void* const* d_in, const int* in_sizes, int n_in,
                              void* d_out, int out_size) {
    (void)in_sizes; (void)n_in; (void)out_size;
    const float* x    = (const float*)d_in[0];
    const float* W1   = (const float*)d_in[1];
    const float* b1   = (const float*)d_in[2];
    const float* Woff = (const float*)d_in[3];
    const float* boff = (const float*)d_in[4];
    const float* Wd   = (const float*)d_in[5];
    const float* bd   = (const float*)d_in[6];
    const float* Wr   = (const float*)d_in[7];
    const float* br   = (const float*)d_in[8];
    float* out = (float*)d_out;

    cudaFuncSetAttribute(conv_f16<0>, cudaFuncAttributeMaxDynamicSharedMemorySize, SMEM_CONV);
    cudaFuncSetAttribute(conv_f16<1>, cudaFuncAttributeMaxDynamicSharedMemorySize, SMEM_CONV);
    cudaFuncSetAttribute(deform_f16,  cudaFuncAttributeMaxDynamicSharedMemorySize, SMEM_DEF);

    prep_weights<<<(KTAP*64*64 + 255)/256, 256>>>(W1, Woff, Wd, Wr);
    prep_x<<<256, 256>>>(x);
    conv_f16<0><<<512, 256, SMEM_CONV>>>(b1);
    conv_f16<1><<<512, 256, SMEM_CONV>>>(boff);
    deform_f16<<<512, 256, SMEM_DEF>>>(bd, br, out);
}

// round 8
// speedup vs baseline: 1.2619x; 1.2619x over previous
#include <cuda_runtime.h>
#include <cuda_fp16.h>
#include <cstdint>

#define TT 8
#define HH 64
#define WWD 64
#define HWX 4096
#define PLANE 32768
#define KTAP 27

// -------- device scratch --------
__device__ __half g_xh[64*PLANE];        // x fp16, [pos][c]
__device__ __half g_y1h[64*PLANE];       // lrelu(conv1) fp16, [pos][c]
__device__ float  g_off[54*PLANE];       // offsets fp32, [o][pos]
__device__ __half g_W1h[KTAP*64*64];     // [tap][o][c]
__device__ __half g_Woffh[KTAP*64*64];
__device__ __half g_Wdh[KTAP*64*64];
__device__ __half g_Wrh[64*64];          // [o][c]

__device__ __forceinline__ uint32_t smem_u32(const void* p){
    uint32_t a;
    asm("{ .reg .u64 t; cvta.to.shared.u64 t, %1; cvt.u32.u64 %0, t; }"
        : "=r"(a) : "l"(p));
    return a;
}
__device__ __forceinline__ void ldsm4(uint32_t& r0,uint32_t& r1,uint32_t& r2,uint32_t& r3, uint32_t addr){
    asm volatile("ldmatrix.sync.aligned.m8n8.x4.shared.b16 {%0,%1,%2,%3}, [%4];"
        : "=r"(r0),"=r"(r1),"=r"(r2),"=r"(r3) : "r"(addr));
}
__device__ __forceinline__ void mma16816(float* d, uint32_t a0,uint32_t a1,uint32_t a2,uint32_t a3,
                                         uint32_t b0,uint32_t b1){
    asm volatile("mma.sync.aligned.m16n8k16.row.col.f32.f16.f16.f32 "
        "{%0,%1,%2,%3},{%4,%5,%6,%7},{%8,%9},{%0,%1,%2,%3};"
        : "+f"(d[0]),"+f"(d[1]),"+f"(d[2]),"+f"(d[3])
        : "r"(a0),"r"(a1),"r"(a2),"r"(a3),"r"(b0),"r"(b1));
}

// half (2 of 4 k16-stages) of one K=64 chunk.
// Block tile: A[128pos x 64k] x B[64ch x 64k]^T. Warp tile m32 (at m0) x n32 (at n0).
// acc tile index: mi*4 + ni*2 + hn  (mi,ni in {0,1}, hn = n8 half)
template<int ST0>
__device__ __forceinline__ void gemm_half(uint32_t Ab, uint32_t Bb, int m0, int n0,
                                          int lane, float acc[8][4]){
    int g = lane>>3, r = lane&7;
    #pragma unroll
    for (int s=0;s<2;s++){
        int st = ST0 + s;
        uint32_t a[2][4], b[2][4];
        #pragma unroll
        for (int mi=0;mi<2;mi++){
            int rowA = m0 + mi*16 + (g&1)*8 + r;
            int segA = st*2 + (g>>1);
            ldsm4(a[mi][0],a[mi][1],a[mi][2],a[mi][3],
                  Ab + rowA*128 + ((segA ^ (rowA&7))<<4));
        }
        #pragma unroll
        for (int ni=0;ni<2;ni++){
            int rowB = n0 + ni*16 + (g>>1)*8 + r;
            int segB = st*2 + (g&1);
            ldsm4(b[ni][0],b[ni][1],b[ni][2],b[ni][3],
                  Bb + rowB*128 + ((segB ^ (rowB&7))<<4));
        }
        #pragma unroll
        for (int mi=0;mi<2;mi++)
        #pragma unroll
        for (int ni=0;ni<2;ni++){
            mma16816(acc[mi*4+ni*2],   a[mi][0],a[mi][1],a[mi][2],a[mi][3], b[ni][0],b[ni][1]);
            mma16816(acc[mi*4+ni*2+1], a[mi][0],a[mi][1],a[mi][2],a[mi][3], b[ni][2],b[ni][3]);
        }
    }
}

__device__ __forceinline__ uint4 bilin8(const uint4* P, const float* W){
    uint4 r;
    const uint32_t* p0 = (const uint32_t*)&P[0];
    const uint32_t* p1 = (const uint32_t*)&P[1];
    const uint32_t* p2 = (const uint32_t*)&P[2];
    const uint32_t* p3 = (const uint32_t*)&P[3];
    uint32_t* ro = (uint32_t*)&r;
    #pragma unroll
    for (int k=0;k<4;k++){
        float2 f0 = __half22float2(*(const __half2*)&p0[k]);
        float2 f1 = __half22float2(*(const __half2*)&p1[k]);
        float2 f2 = __half22float2(*(const __half2*)&p2[k]);
        float2 f3 = __half22float2(*(const __half2*)&p3[k]);
        float vx = W[0]*f0.x + W[1]*f1.x + W[2]*f2.x + W[3]*f3.x;
        float vy = W[0]*f0.y + W[1]*f1.y + W[2]*f2.y + W[3]*f3.y;
        __half2 h = __floats2half2_rn(vx, vy);
        ro[k] = *(uint32_t*)&h;
    }
    return r;
}

// -------- prep --------
__global__ void prep_weights(const float* __restrict__ W1, const float* __restrict__ Woff,
                             const float* __restrict__ Wd, const float* __restrict__ Wr){
    int i = blockIdx.x*256 + threadIdx.x;
    if (i < KTAP*64*64){
        int tap = i>>12, o = (i>>6)&63, c = i&63;
        int src = o*1728 + c*27 + tap;
        g_W1h[i] = __float2half(W1[src]);
        g_Wdh[i] = __float2half(Wd[src]);
        g_Woffh[i] = (o < 54) ? __float2half(Woff[src]) : __half(0.f);
        if (i < 64*64) g_Wrh[i] = __float2half(Wr[i]);
    }
}

__global__ void prep_x(const float* __restrict__ x){
    __shared__ __half sT[128*72];
    int tid = threadIdx.x;
    int pos0 = blockIdx.x*128;
    int p = tid & 127, ch0 = tid >> 7;
    #pragma unroll 8
    for (int cc = 0; cc < 32; cc++){
        int c = cc*2 + ch0;
        sT[p*72 + c] = __float2half(x[c*PLANE + pos0 + p]);
    }
    __syncthreads();
    int oc = tid & 7;
    #pragma unroll
    for (int j = 0; j < 4; j++){
        int n = (tid>>3) + j*32;
        uint4 v = *(uint4*)&sT[n*72 + oc*8];
        *(uint4*)&g_xh[(pos0+n)*64 + oc*8] = v;
    }
}

// ==================== conv 3x3x3, N=128, pipelined ====================
// smem: misc[0,1024) | SA0@1024(16K) SA1@17408(16K) SB0@33792(8K) SB1@41984(8K) end 50176
// epilogue aliases @1024
#define SMEM_CONV 50176
template<int MODE>   // 0: xh -> y1h (lrelu); 1: y1h -> g_off (54 ch)
__global__ void __launch_bounds__(256)
conv_f16(const float* __restrict__ bias)
{
    extern __shared__ char sm[];
    float* sBias = (float*)sm;
    char* SA0 = sm + 1024;
    char* SA1 = sm + 17408;
    char* SB0 = sm + 33792;
    char* SB1 = sm + 41984;
    uint32_t sbase = smem_u32(sm);
    const __half* src  = (MODE==0)? g_xh  : g_y1h;
    const __half* Wall = (MODE==0)? g_W1h : g_Woffh;

    int tid = threadIdx.x, lane = tid&31, wid = tid>>5;
    int t = blockIdx.x>>5, h0 = (blockIdx.x&31)<<1;
    if (tid < 64) sBias[tid] = (MODE==0 || tid<54)? bias[tid] : 0.f;

    int oc = tid&7;
    int o_w = tid>>2, part = tid&3, s0w = part*2;
    int m0 = (wid&3)*32, n0 = (wid>>2)*32;
    float acc[8][4];
    #pragma unroll
    for (int i=0;i<8;i++){ acc[i][0]=0.f; acc[i][1]=0.f; acc[i][2]=0.f; acc[i][3]=0.f; }

    uint4 Av[4], Bv0, Bv1;
    #define CONV_LDG(tap) do{ \
        int kt=(tap)/9, rr=(tap)-kt*9, kh=rr/3, kw=rr-kh*3; \
        int t_in = t-1+kt; \
        _Pragma("unroll") \
        for (int jj=0;jj<4;jj++){ \
            int n = (tid>>3) + jj*32; \
            int hh = n>>6, w = n&63; \
            int h_in = h0+hh-1+kh, w_in = w-1+kw; \
            bool valid = ((unsigned)t_in<TT)&&((unsigned)h_in<HH)&&((unsigned)w_in<WWD); \
            Av[jj] = make_uint4(0,0,0,0); \
            if (valid) Av[jj] = *(const uint4*)&src[(t_in*HWX + h_in*WWD + w_in)*64 + oc*8]; \
        } \
        const uint4* sp = (const uint4*)(Wall + (tap)*4096 + o_w*64 + part*16); \
        Bv0 = sp[0]; Bv1 = sp[1]; \
    } while(0)
    #define CONV_STS(SA, SB) do{ \
        _Pragma("unroll") \
        for (int jj=0;jj<4;jj++){ \
            int n = (tid>>3) + jj*32; \
            *(uint4*)((SA) + n*128 + ((oc ^ (n&7))<<4)) = Av[jj]; \
        } \
        *(uint4*)((SB) + o_w*128 + ((s0w ^ (o_w&7))<<4)) = Bv0; \
        *(uint4*)((SB) + o_w*128 + (((s0w+1)^(o_w&7))<<4)) = Bv1; \
    } while(0)

    CONV_LDG(0);
    CONV_STS(SA0, SB0);
    __syncthreads();

    for (int tap=0; tap<KTAP; tap++){
        int p = tap&1;
        uint32_t Ab = sbase + (p ? 17408 : 1024);
        uint32_t Bb = sbase + (p ? 41984 : 33792);
        bool more = (tap+1) < KTAP;
        if (more) CONV_LDG(tap+1);
        gemm_half<0>(Ab,Bb,m0,n0,lane,acc);
        if (more){
            char* SAn = p ? SA0 : SA1;
            char* SBn = p ? SB0 : SB1;
            CONV_STS(SAn, SBn);
        }
        gemm_half<2>(Ab,Bb,m0,n0,lane,acc);
        __syncthreads();
    }

    int q = lane>>2, c2 = (lane&3)<<1;
    int base = t*HWX + h0*WWD;
    if (MODE==0){
        uint32_t* sOutH2 = (uint32_t*)(sm + 1024);  // [pos][36] half2
        #pragma unroll
        for (int t8=0;t8<8;t8++){
            int mi=t8>>2, ni=(t8>>1)&1, hn=t8&1;
            int o = n0 + ni*16 + hn*8 + c2;
            int r0 = m0 + mi*16 + q;
            float b0v = sBias[o], b1v = sBias[o+1];
            float v0 = acc[t8][0]+b0v, v1 = acc[t8][1]+b1v;
            float v2 = acc[t8][2]+b0v, v3 = acc[t8][3]+b1v;
            v0 = v0>=0.f?v0:0.01f*v0; v1 = v1>=0.f?v1:0.01f*v1;
            v2 = v2>=0.f?v2:0.01f*v2; v3 = v3>=0.f?v3:0.01f*v3;
            __half2 h01 = __floats2half2_rn(v0,v1);
            __half2 h23 = __floats2half2_rn(v2,v3);
            sOutH2[r0*36     + (o>>1)] = *(uint32_t*)&h01;
            sOutH2[(r0+8)*36 + (o>>1)] = *(uint32_t*)&h23;
        }
        __syncthreads();
        __half* sOutH = (__half*)(sm + 1024);
        #pragma unroll
        for (int jj=0;jj<4;jj++){
            int n = (tid>>3) + jj*32;
            uint4 v = *(uint4*)&sOutH[n*72 + oc*8];
            *(uint4*)&g_y1h[(base+n)*64 + oc*8] = v;
        }
    } else {
        float* sOut = (float*)(sm + 1024);   // [o][132]
        #pragma unroll
        for (int t8=0;t8<8;t8++){
            int mi=t8>>2, ni=(t8>>1)&1, hn=t8&1;
            int o = n0 + ni*16 + hn*8 + c2;
            int nn = m0 + mi*16 + q;
            float b0v = sBias[o], b1v = sBias[o+1];
            sOut[o*132+nn]       = acc[t8][0]+b0v;
            sOut[(o+1)*132+nn]   = acc[t8][1]+b1v;
            sOut[o*132+nn+8]     = acc[t8][2]+b0v;
            sOut[(o+1)*132+nn+8] = acc[t8][3]+b1v;
        }
        __syncthreads();
        int n4 = (tid&31)*4;
        #pragma unroll
        for (int i=0;i<8;i++){
            int o = (tid>>5) + i*8;
            if (o < 54){
                float4 v = *(float4*)&sOut[o*132+n4];
                *(float4*)&g_off[o*PLANE + base + n4] = v;
            }
        }
    }
    #undef CONV_LDG
    #undef CONV_STS
}

// ==================== deformable conv + residual + lrelu, N=128, pipelined ====================
// smem: misc[0,1024) | SA0@1024 SA1@17408 SB0@33792 SB1@41984 | tab@50176 (27648) end 77824
// fp32 sOut [o][132] aliases @1024
#define SMEM_DEF 77824

__device__ __forceinline__ void dledg(int tap, int tid, const uint2* sTab,
                                      uint4 P[2][4], float W[2][4], int j0){
    int oc = tid&7;
    #pragma unroll
    for (int jj=0;jj<2;jj++){
        int n = (tid>>3) + (j0+jj)*32;
        uint2 tb = sTab[tap*128 + n];
        uint32_t pk = tb.x;
        __half2 fhw = *(__half2*)&tb.y;
        float fh = __low2float(fhw), fw = __high2float(fhw);
        int wb = (int)(pk&127)-2, hb = (int)((pk>>7)&127)-2;
        int tc = (int)((pk>>14)&7);
        unsigned mask = pk>>17;
        float w00=(1.f-fh)*(1.f-fw), w01=(1.f-fh)*fw, w10=fh*(1.f-fw), w11=fh*fw;
        if(!(mask&1u)) w00=0.f;
        if(!(mask&2u)) w01=0.f;
        if(!(mask&4u)) w10=0.f;
        if(!(mask&8u)) w11=0.f;
        int ih0=min(max(hb,0),HH-1),  ih1=min(max(hb+1,0),HH-1);
        int iw0=min(max(wb,0),WWD-1), iw1=min(max(wb+1,0),WWD-1);
        int b0 = tc*HWX;
        P[jj][0] = *(const uint4*)&g_y1h[(b0+ih0*WWD+iw0)*64 + oc*8];
        P[jj][1] = *(const uint4*)&g_y1h[(b0+ih0*WWD+iw1)*64 + oc*8];
        P[jj][2] = *(const uint4*)&g_y1h[(b0+ih1*WWD+iw0)*64 + oc*8];
        P[jj][3] = *(const uint4*)&g_y1h[(b0+ih1*WWD+iw1)*64 + oc*8];
        W[jj][0]=w00; W[jj][1]=w01; W[jj][2]=w10; W[jj][3]=w11;
    }
}
__device__ __forceinline__ void rledg(int tid, int base_p, uint4 P[2][4], float W[2][4], int j0){
    int oc = tid&7;
    #pragma unroll
    for (int jj=0;jj<2;jj++){
        int n = (tid>>3) + (j0+jj)*32;
        P[jj][0] = *(const uint4*)&g_xh[(base_p+n)*64 + oc*8];
        P[jj][1] = make_uint4(0,0,0,0);
        P[jj][2] = make_uint4(0,0,0,0);
        P[jj][3] = make_uint4(0,0,0,0);
        W[jj][0]=1.f; W[jj][1]=0.f; W[jj][2]=0.f; W[jj][3]=0.f;
    }
}
__device__ __forceinline__ void dlsts(char* SA, int tid, uint4 P[2][4], float W[2][4], int j0){
    int oc = tid&7;
    #pragma unroll
    for (int jj=0;jj<2;jj++){
        int n = (tid>>3) + (j0+jj)*32;
        uint4 r = bilin8(P[jj], W[jj]);
        *(uint4*)(SA + n*128 + ((oc ^ (n&7))<<4)) = r;
    }
}

__global__ void __launch_bounds__(256)
deform_f16(const float* __restrict__ bd, const float* __restrict__ br,
           float* __restrict__ out)
{
    extern __shared__ char sm[];
    float* sBd = (float*)sm;
    float* sBr = (float*)(sm + 256);
    char* SA0 = sm + 1024;
    char* SA1 = sm + 17408;
    char* SB0 = sm + 33792;
    char* SB1 = sm + 41984;
    uint2* sTab = (uint2*)(sm + 50176);
    uint32_t sbase = smem_u32(sm);

    int tid = threadIdx.x, lane = tid&31, wid = tid>>5;
    int t = blockIdx.x>>5, h0 = (blockIdx.x&31)<<1;
    if (tid < 64){ sBd[tid] = bd[tid]; sBr[tid] = br[tid]; }

    // bilinear tap table (8B per (tap,n)), computed once, reused by all channels
    for (int e = tid; e < KTAP*128; e += 256){
        int tap = e>>7, n = e&127;
        int hh = n>>6, w = n&63;
        int h = h0 + hh;
        int kt = tap/9, rr = tap-kt*9, kh = rr/3, kw = rr-kh*3;
        int t_in = t-1+kt;
        bool t_ok = (unsigned)t_in < TT;
        int t_c = min(max(t_in,0),TT-1);
        int pidx = t*HWX + h*WWD + w;
        float dh = g_off[(2*tap)*PLANE + pidx];
        float dw = g_off[(2*tap+1)*PLANE + pidx];
        float h_s = (float)(h-1+kh)+dh, w_s = (float)(w-1+kw)+dw;
        float h0f = floorf(h_s), w0f = floorf(w_s);
        float fh = h_s-h0f, fw = w_s-w0f;
        int hb = (int)h0f, wb = (int)w0f;
        unsigned mask = 0;
        if (t_ok){
            unsigned h0ok = ((unsigned)hb < HH),  h1ok = ((unsigned)(hb+1) < HH);
            unsigned w0ok = ((unsigned)wb < WWD), w1ok = ((unsigned)(wb+1) < WWD);
            mask = (h0ok&w0ok) | ((h0ok&w1ok)<<1) | ((h1ok&w0ok)<<2) | ((h1ok&w1ok)<<3);
        }
        int hbc = min(max(hb,-2),64), wbc = min(max(wb,-2),64);
        uint32_t pack = (uint32_t)(wbc+2) | ((uint32_t)(hbc+2)<<7) | ((uint32_t)t_c<<14) | (mask<<17);
        __half2 f2 = __floats2half2_rn(fh, fw);
        sTab[e] = make_uint2(pack, *(uint32_t*)&f2);
    }
    __syncthreads();

    int m0 = (wid&3)*32, n0 = (wid>>2)*32;
    int base_p = t*HWX + h0*WWD;
    float acc[8][4];
    #pragma unroll
    for (int i=0;i<8;i++){ acc[i][0]=0.f; acc[i][1]=0.f; acc[i][2]=0.f; acc[i][3]=0.f; }

    int o_w = tid>>2, part = tid&3, s0w = part*2;

    // prologue: stage chunk 0 into buffer 0
    {
        uint4 P[2][4]; float W[2][4];
        dledg(0, tid, sTab, P, W, 0); dlsts(SA0, tid, P, W, 0);
        dledg(0, tid, sTab, P, W, 2); dlsts(SA0, tid, P, W, 2);
        const uint4* sp = (const uint4*)(g_Wdh + o_w*64 + part*16);
        uint4 wv0 = sp[0], wv1 = sp[1];
        *(uint4*)(SB0 + o_w*128 + ((s0w ^ (o_w&7))<<4)) = wv0;
        *(uint4*)(SB0 + o_w*128 + (((s0w+1)^(o_w&7))<<4)) = wv1;
    }
    __syncthreads();

    int q = lane>>2, c2 = (lane&3)<<1;
    // 28 chunks: taps 0..26 + residual (27)
    for (int it = 0; it < 28; it++){
        int p = it & 1;
        uint32_t Ab = sbase + (p ? 17408 : 1024);
        uint32_t Bb = sbase + (p ? 41984 : 33792);
        char* SAn = p ? SA0 : SA1;
        char* SBn = p ? SB0 : SB1;
        int nxt = it + 1;
        bool more = nxt < 28;

        uint4 P[2][4]; float W[2][4];
        uint4 wv0, wv1;
        if (more){
            if (nxt < 27) dledg(nxt, tid, sTab, P, W, 0);
            else          rledg(tid, base_p, P, W, 0);
            const __half* Wsrc = (nxt < 27) ? (g_Wdh + nxt*4096) : g_Wrh;
            const uint4* sp = (const uint4*)(Wsrc + o_w*64 + part*16);
            wv0 = sp[0]; wv1 = sp[1];
        }
        gemm_half<0>(Ab, Bb, m0, n0, lane, acc);
        if (more){
            dlsts(SAn, tid, P, W, 0);
            if (nxt < 27) dledg(nxt, tid, sTab, P, W, 2);
            else          rledg(tid, base_p, P, W, 2);
        }
        gemm_half<2>(Ab, Bb, m0, n0, lane, acc);
        if (more){
            dlsts(SAn, tid, P, W, 2);
            *(uint4*)(SBn + o_w*128 + ((s0w ^ (o_w&7))<<4)) = wv0;
            *(uint4*)(SBn + o_w*128 + (((s0w+1)^(o_w&7))<<4)) = wv1;
        }
        if (it == 26){
            // fold deform bias + lrelu before the residual chunk
            #pragma unroll
            for (int t8=0;t8<8;t8++){
                int ni=(t8>>1)&1, hn=t8&1;
                int o = n0 + ni*16 + hn*8 + c2;
                float b0v = sBd[o], b1v = sBd[o+1];
                float v;
                v = acc[t8][0]+b0v; acc[t8][0] = v>=0.f?v:0.01f*v;
                v = acc[t8][1]+b1v; acc[t8][1] = v>=0.f?v:0.01f*v;
                v = acc[t8][2]+b0v; acc[t8][2] = v>=0.f?v:0.01f*v;
                v = acc[t8][3]+b1v; acc[t8][3] = v>=0.f?v:0.01f*v;
            }
        }
        __syncthreads();
    }

    // epilogue: + br, transpose, coalesced stores
    float* sOut = (float*)(sm + 1024);  // [o][132]
    #pragma unroll
    for (int t8=0;t8<8;t8++){
        int mi=t8>>2, ni=(t8>>1)&1, hn=t8&1;
        int o = n0 + ni*16 + hn*8 + c2;
        int nn = m0 + mi*16 + q;
        float b0v = sBr[o], b1v = sBr[o+1];
        sOut[o*132+nn]       = acc[t8][0]+b0v;
        sOut[(o+1)*132+nn]   = acc[t8][1]+b1v;
        sOut[o*132+nn+8]     = acc[t8][2]+b0v;
        sOut[(o+1)*132+nn+8] = acc[t8][3]+b1v;
    }
    __syncthreads();
    int n4 = (tid&31)*4;
    #pragma unroll
    for (int i=0;i<8;i++){
        int o = (tid>>5) + i*8;
        float4 v = *(float4*)&sOut[o*132+n4];
        *(float4*)&out[o*PLANE + base_p + n4] = v;
    }
}

// -------- launch --------
extern "C" void kernel_launch(void* const* d_in, const int* in_sizes, int n_in,
                              void* d_out, int out_size) {
    (void)in_sizes; (void)n_in; (void)out_size;
    const float* x    = (const float*)d_in[0];
    const float* W1   = (const float*)d_in[1];
    const float* b1   = (const float*)d_in[2];
    const float* Woff = (const float*)d_in[3];
    const float* boff = (const float*)d_in[4];
    const float* Wd   = (const float*)d_in[5];
    const float* bd   = (const float*)d_in[6];
    const float* Wr   = (const float*)d_in[7];
    const float* br   = (const float*)d_in[8];
    float* out = (float*)d_out;

    cudaFuncSetAttribute(conv_f16<0>, cudaFuncAttributeMaxDynamicSharedMemorySize, SMEM_CONV);
    cudaFuncSetAttribute(conv_f16<1>, cudaFuncAttributeMaxDynamicSharedMemorySize, SMEM_CONV);
    cudaFuncSetAttribute(deform_f16,  cudaFuncAttributeMaxDynamicSharedMemorySize, SMEM_DEF);

    prep_weights<<<(KTAP*64*64 + 255)/256, 256>>>(W1, Woff, Wd, Wr);
    prep_x<<<256, 256>>>(x);
    conv_f16<0><<<256, 256, SMEM_CONV>>>(b1);
    conv_f16<1><<<256, 256, SMEM_CONV>>>(boff);
    deform_f16<<<256, 256, SMEM_DEF>>>(bd, br, out);
}

// round 9
// speedup vs baseline: 1.3305x; 1.0544x over previous
#include <cuda_runtime.h>
#include <cuda_fp16.h>
#include <cstdint>

#define TT 8
#define HH 64
#define WWD 64
#define HWX 4096
#define PLANE 32768
#define KTAP 27

// -------- device scratch --------
__device__ __half g_xh[64*PLANE];        // x fp16, [pos][c]
__device__ __half g_y1h[64*PLANE];       // lrelu(conv1) fp16, [pos][c]
__device__ float  g_off[54*PLANE];       // offsets fp32, [o][pos]
__device__ __half g_W1h[KTAP*64*64];     // [tap][o][c]
__device__ __half g_Woffh[KTAP*64*64];
__device__ __half g_Wdh[KTAP*64*64];
__device__ __half g_Wrh[64*64];          // [o][c]

__device__ __forceinline__ uint32_t smem_u32(const void* p){
    uint32_t a;
    asm("{ .reg .u64 t; cvta.to.shared.u64 t, %1; cvt.u32.u64 %0, t; }"
        : "=r"(a) : "l"(p));
    return a;
}
__device__ __forceinline__ void ldsm4(uint32_t& r0,uint32_t& r1,uint32_t& r2,uint32_t& r3, uint32_t addr){
    asm volatile("ldmatrix.sync.aligned.m8n8.x4.shared.b16 {%0,%1,%2,%3}, [%4];"
        : "=r"(r0),"=r"(r1),"=r"(r2),"=r"(r3) : "r"(addr));
}
__device__ __forceinline__ void mma16816(float* d, uint32_t a0,uint32_t a1,uint32_t a2,uint32_t a3,
                                         uint32_t b0,uint32_t b1){
    asm volatile("mma.sync.aligned.m16n8k16.row.col.f32.f16.f16.f32 "
        "{%0,%1,%2,%3},{%4,%5,%6,%7},{%8,%9},{%0,%1,%2,%3};"
        : "+f"(d[0]),"+f"(d[1]),"+f"(d[2]),"+f"(d[3])
        : "r"(a0),"r"(a1),"r"(a2),"r"(a3),"r"(b0),"r"(b1));
}

// ---- conv gemm: A read straight from input window (row offset woff), B from staged tile ----
// warp tile m32 x n32 ; acc index mi*4 + ni*2 + hn
template<int ST0>
__device__ __forceinline__ void gemm_conv(uint32_t WinB, int woff, uint32_t Bb, int n0,
                                          int lane, float acc[8][4]){
    int g = lane>>3, r = lane&7;
    #pragma unroll
    for (int s=0;s<2;s++){
        int st = ST0 + s;
        uint32_t a[2][4], b[2][4];
        #pragma unroll
        for (int mi=0;mi<2;mi++){
            int rowA = woff + mi*16 + (g&1)*8 + r;
            int segA = st*2 + (g>>1);
            ldsm4(a[mi][0],a[mi][1],a[mi][2],a[mi][3],
                  WinB + rowA*128 + ((segA ^ (rowA&7))<<4));
        }
        #pragma unroll
        for (int ni=0;ni<2;ni++){
            int rowB = n0 + ni*16 + (g>>1)*8 + r;
            int segB = st*2 + (g&1);
            ldsm4(b[ni][0],b[ni][1],b[ni][2],b[ni][3],
                  Bb + rowB*128 + ((segB ^ (rowB&7))<<4));
        }
        #pragma unroll
        for (int mi=0;mi<2;mi++)
        #pragma unroll
        for (int ni=0;ni<2;ni++){
            mma16816(acc[mi*4+ni*2],   a[mi][0],a[mi][1],a[mi][2],a[mi][3], b[ni][0],b[ni][1]);
            mma16816(acc[mi*4+ni*2+1], a[mi][0],a[mi][1],a[mi][2],a[mi][3], b[ni][2],b[ni][3]);
        }
    }
}

// ---- deform gemm: both tiles staged (same as R8) ----
template<int ST0>
__device__ __forceinline__ void gemm_half(uint32_t Ab, uint32_t Bb, int m0, int n0,
                                          int lane, float acc[8][4]){
    int g = lane>>3, r = lane&7;
    #pragma unroll
    for (int s=0;s<2;s++){
        int st = ST0 + s;
        uint32_t a[2][4], b[2][4];
        #pragma unroll
        for (int mi=0;mi<2;mi++){
            int rowA = m0 + mi*16 + (g&1)*8 + r;
            int segA = st*2 + (g>>1);
            ldsm4(a[mi][0],a[mi][1],a[mi][2],a[mi][3],
                  Ab + rowA*128 + ((segA ^ (rowA&7))<<4));
        }
        #pragma unroll
        for (int ni=0;ni<2;ni++){
            int rowB = n0 + ni*16 + (g>>1)*8 + r;
            int segB = st*2 + (g&1);
            ldsm4(b[ni][0],b[ni][1],b[ni][2],b[ni][3],
                  Bb + rowB*128 + ((segB ^ (rowB&7))<<4));
        }
        #pragma unroll
        for (int mi=0;mi<2;mi++)
        #pragma unroll
        for (int ni=0;ni<2;ni++){
            mma16816(acc[mi*4+ni*2],   a[mi][0],a[mi][1],a[mi][2],a[mi][3], b[ni][0],b[ni][1]);
            mma16816(acc[mi*4+ni*2+1], a[mi][0],a[mi][1],a[mi][2],a[mi][3], b[ni][2],b[ni][3]);
        }
    }
}

__device__ __forceinline__ uint4 bilin8(const uint4* P, const float* W){
    uint4 r;
    const uint32_t* p0 = (const uint32_t*)&P[0];
    const uint32_t* p1 = (const uint32_t*)&P[1];
    const uint32_t* p2 = (const uint32_t*)&P[2];
    const uint32_t* p3 = (const uint32_t*)&P[3];
    uint32_t* ro = (uint32_t*)&r;
    #pragma unroll
    for (int k=0;k<4;k++){
        float2 f0 = __half22float2(*(const __half2*)&p0[k]);
        float2 f1 = __half22float2(*(const __half2*)&p1[k]);
        float2 f2 = __half22float2(*(const __half2*)&p2[k]);
        float2 f3 = __half22float2(*(const __half2*)&p3[k]);
        float vx = W[0]*f0.x + W[1]*f1.x + W[2]*f2.x + W[3]*f3.x;
        float vy = W[0]*f0.y + W[1]*f1.y + W[2]*f2.y + W[3]*f3.y;
        __half2 h = __floats2half2_rn(vx, vy);
        ro[k] = *(uint32_t*)&h;
    }
    return r;
}

// -------- prep --------
__global__ void prep_weights(const float* __restrict__ W1, const float* __restrict__ Woff,
                             const float* __restrict__ Wd, const float* __restrict__ Wr){
    int i = blockIdx.x*256 + threadIdx.x;
    if (i < KTAP*64*64){
        int tap = i>>12, o = (i>>6)&63, c = i&63;
        int src = o*1728 + c*27 + tap;
        g_W1h[i] = __float2half(W1[src]);
        g_Wdh[i] = __float2half(Wd[src]);
        g_Woffh[i] = (o < 54) ? __float2half(Woff[src]) : __half(0.f);
        if (i < 64*64) g_Wrh[i] = __float2half(Wr[i]);
    }
}

__global__ void prep_x(const float* __restrict__ x){
    __shared__ __half sT[128*72];
    int tid = threadIdx.x;
    int pos0 = blockIdx.x*128;
    int p = tid & 127, ch0 = tid >> 7;
    #pragma unroll 8
    for (int cc = 0; cc < 32; cc++){
        int c = cc*2 + ch0;
        sT[p*72 + c] = __float2half(x[c*PLANE + pos0 + p]);
    }
    __syncthreads();
    int oc = tid & 7;
    #pragma unroll
    for (int j = 0; j < 4; j++){
        int n = (tid>>3) + j*32;
        uint4 v = *(uint4*)&sT[n*72 + oc*8];
        *(uint4*)&g_xh[(pos0+n)*64 + oc*8] = v;
    }
}

// ==================== conv 3x3x3, window-cached A ====================
// smem: misc[0,1024) | WIN@1024 (264*128 = 33792) | SB0@34816(8K) | SB1@43008(8K) end 51200
// epilogue aliases @1024
#define SMEM_CONV 51200
template<int MODE>   // 0: xh -> y1h (lrelu); 1: y1h -> g_off (54 ch)
__global__ void __launch_bounds__(256)
conv_f16(const float* __restrict__ bias)
{
    extern __shared__ char sm[];
    float* sBias = (float*)sm;
    char* WIN = sm + 1024;
    char* SB0 = sm + 34816;
    char* SB1 = sm + 43008;
    uint32_t sbase = smem_u32(sm);
    uint32_t WinB = sbase + 1024;
    const __half* src  = (MODE==0)? g_xh  : g_y1h;
    const __half* Wall = (MODE==0)? g_W1h : g_Woffh;

    int tid = threadIdx.x, lane = tid&31, wid = tid>>5;
    int t = blockIdx.x>>5, h0 = (blockIdx.x&31)<<1;
    if (tid < 64) sBias[tid] = (MODE==0 || tid<54)? bias[tid] : 0.f;

    int o_w = tid>>2, part = tid&3, s0w = part*2;
    int m0 = (wid&3)*32, n0 = (wid>>2)*32;
    float acc[8][4];
    #pragma unroll
    for (int i=0;i<8;i++){ acc[i][0]=0.f; acc[i][1]=0.f; acc[i][2]=0.f; acc[i][3]=0.f; }

    // stage B tap 0
    uint4 Bv0, Bv1;
    {
        const uint4* sp = (const uint4*)(Wall + o_w*64 + part*16);
        Bv0 = sp[0]; Bv1 = sp[1];
        *(uint4*)(SB0 + o_w*128 + ((s0w ^ (o_w&7))<<4)) = Bv0;
        *(uint4*)(SB0 + o_w*128 + (((s0w+1)^(o_w&7))<<4)) = Bv1;
    }

    int whh = (m0>>6)*66 + (m0&63);   // warp-constant window row base (before kh/kw shift)

    for (int kt=0; kt<3; kt++){
        int t_in = t-1+kt;
        bool tok = (unsigned)t_in < TT;
        // load the fp16 input window [4h][66w][64c], swizzled, zero halo
        for (int e = tid; e < 2112; e += 256){
            int pos = e >> 3, seg = e & 7;
            int hr = pos/66, wc = pos - hr*66;
            int h_in = h0 + hr - 1, w_in = wc - 1;
            uint4 v = make_uint4(0,0,0,0);
            if (tok && (unsigned)h_in < HH && (unsigned)w_in < WWD)
                v = *(const uint4*)&src[(t_in*HWX + h_in*WWD + w_in)*64 + seg*8];
            *(uint4*)(WIN + pos*128 + ((seg ^ (pos&7))<<4)) = v;
        }
        __syncthreads();
        for (int j=0;j<9;j++){
            int tap = kt*9 + j;
            uint32_t Bb = sbase + ((tap&1) ? 43008 : 34816);
            bool more = (tap+1) < KTAP;
            if (more){
                const uint4* sp = (const uint4*)(Wall + (tap+1)*4096 + o_w*64 + part*16);
                Bv0 = sp[0]; Bv1 = sp[1];
            }
            int kh = j/3, kw = j - kh*3;
            int woff = whh + kh*66 + kw;
            gemm_conv<0>(WinB, woff, Bb, n0, lane, acc);
            if (more){
                char* SBx = ((tap+1)&1) ? SB1 : SB0;
                *(uint4*)(SBx + o_w*128 + ((s0w ^ (o_w&7))<<4)) = Bv0;
                *(uint4*)(SBx + o_w*128 + (((s0w+1)^(o_w&7))<<4)) = Bv1;
            }
            gemm_conv<2>(WinB, woff, Bb, n0, lane, acc);
            __syncthreads();
        }
    }

    int q = lane>>2, c2 = (lane&3)<<1;
    int base = t*HWX + h0*WWD;
    int oc = tid&7;
    if (MODE==0){
        uint32_t* sOutH2 = (uint32_t*)(sm + 1024);  // [pos][36] half2
        #pragma unroll
        for (int t8=0;t8<8;t8++){
            int mi=t8>>2, ni=(t8>>1)&1, hn=t8&1;
            int o = n0 + ni*16 + hn*8 + c2;
            int r0 = m0 + mi*16 + q;
            float b0v = sBias[o], b1v = sBias[o+1];
            float v0 = acc[t8][0]+b0v, v1 = acc[t8][1]+b1v;
            float v2 = acc[t8][2]+b0v, v3 = acc[t8][3]+b1v;
            v0 = v0>=0.f?v0:0.01f*v0; v1 = v1>=0.f?v1:0.01f*v1;
            v2 = v2>=0.f?v2:0.01f*v2; v3 = v3>=0.f?v3:0.01f*v3;
            __half2 h01 = __floats2half2_rn(v0,v1);
            __half2 h23 = __floats2half2_rn(v2,v3);
            sOutH2[r0*36     + (o>>1)] = *(uint32_t*)&h01;
            sOutH2[(r0+8)*36 + (o>>1)] = *(uint32_t*)&h23;
        }
        __syncthreads();
        __half* sOutH = (__half*)(sm + 1024);
        #pragma unroll
        for (int jj=0;jj<4;jj++){
            int n = (tid>>3) + jj*32;
            uint4 v = *(uint4*)&sOutH[n*72 + oc*8];
            *(uint4*)&g_y1h[(base+n)*64 + oc*8] = v;
        }
    } else {
        float* sOut = (float*)(sm + 1024);   // [o][132]
        #pragma unroll
        for (int t8=0;t8<8;t8++){
            int mi=t8>>2, ni=(t8>>1)&1, hn=t8&1;
            int o = n0 + ni*16 + hn*8 + c2;
            int nn = m0 + mi*16 + q;
            float b0v = sBias[o], b1v = sBias[o+1];
            sOut[o*132+nn]       = acc[t8][0]+b0v;
            sOut[(o+1)*132+nn]   = acc[t8][1]+b1v;
            sOut[o*132+nn+8]     = acc[t8][2]+b0v;
            sOut[(o+1)*132+nn+8] = acc[t8][3]+b1v;
        }
        __syncthreads();
        int n4 = (tid&31)*4;
        #pragma unroll
        for (int i=0;i<8;i++){
            int o = (tid>>5) + i*8;
            if (o < 54){
                float4 v = *(float4*)&sOut[o*132+n4];
                *(float4*)&g_off[o*PLANE + base + n4] = v;
            }
        }
    }
}

// ==================== deformable conv + residual + lrelu (R8 structure) ====================
// smem: misc[0,1024) | SA0@1024 SA1@17408 SB0@33792 SB1@41984 | tab@50176 (27648) end 77824
#define SMEM_DEF 77824

__device__ __forceinline__ void dledg(int tap, int tid, const uint2* sTab,
                                      uint4 P[2][4], float W[2][4], int j0){
    int oc = tid&7;
    #pragma unroll
    for (int jj=0;jj<2;jj++){
        int n = (tid>>3) + (j0+jj)*32;
        uint2 tb = sTab[tap*128 + n];
        uint32_t pk = tb.x;
        __half2 fhw = *(__half2*)&tb.y;
        float fh = __low2float(fhw), fw = __high2float(fhw);
        int wb = (int)(pk&127)-2, hb = (int)((pk>>7)&127)-2;
        int tc = (int)((pk>>14)&7);
        unsigned mask = pk>>17;
        float w00=(1.f-fh)*(1.f-fw), w01=(1.f-fh)*fw, w10=fh*(1.f-fw), w11=fh*fw;
        if(!(mask&1u)) w00=0.f;
        if(!(mask&2u)) w01=0.f;
        if(!(mask&4u)) w10=0.f;
        if(!(mask&8u)) w11=0.f;
        int ih0=min(max(hb,0),HH-1),  ih1=min(max(hb+1,0),HH-1);
        int iw0=min(max(wb,0),WWD-1), iw1=min(max(wb+1,0),WWD-1);
        int b0 = tc*HWX;
        P[jj][0] = *(const uint4*)&g_y1h[(b0+ih0*WWD+iw0)*64 + oc*8];
        P[jj][1] = *(const uint4*)&g_y1h[(b0+ih0*WWD+iw1)*64 + oc*8];
        P[jj][2] = *(const uint4*)&g_y1h[(b0+ih1*WWD+iw0)*64 + oc*8];
        P[jj][3] = *(const uint4*)&g_y1h[(b0+ih1*WWD+iw1)*64 + oc*8];
        W[jj][0]=w00; W[jj][1]=w01; W[jj][2]=w10; W[jj][3]=w11;
    }
}
__device__ __forceinline__ void rledg(int tid, int base_p, uint4 P[2][4], float W[2][4], int j0){
    int oc = tid&7;
    #pragma unroll
    for (int jj=0;jj<2;jj++){
        int n = (tid>>3) + (j0+jj)*32;
        P[jj][0] = *(const uint4*)&g_xh[(base_p+n)*64 + oc*8];
        P[jj][1] = make_uint4(0,0,0,0);
        P[jj][2] = make_uint4(0,0,0,0);
        P[jj][3] = make_uint4(0,0,0,0);
        W[jj][0]=1.f; W[jj][1]=0.f; W[jj][2]=0.f; W[jj][3]=0.f;
    }
}
__device__ __forceinline__ void dlsts(char* SA, int tid, uint4 P[2][4], float W[2][4], int j0){
    int oc = tid&7;
    #pragma unroll
    for (int jj=0;jj<2;jj++){
        int n = (tid>>3) + (j0+jj)*32;
        uint4 r = bilin8(P[jj], W[jj]);
        *(uint4*)(SA + n*128 + ((oc ^ (n&7))<<4)) = r;
    }
}

__global__ void __launch_bounds__(256)
deform_f16(const float* __restrict__ bd, const float* __restrict__ br,
           float* __restrict__ out)
{
    extern __shared__ char sm[];
    float* sBd = (float*)sm;
    float* sBr = (float*)(sm + 256);
    char* SA0 = sm + 1024;
    char* SA1 = sm + 17408;
    char* SB0 = sm + 33792;
    char* SB1 = sm + 41984;
    uint2* sTab = (uint2*)(sm + 50176);
    uint32_t sbase = smem_u32(sm);

    int tid = threadIdx.x, lane = tid&31, wid = tid>>5;
    int t = blockIdx.x>>5, h0 = (blockIdx.x&31)<<1;
    if (tid < 64){ sBd[tid] = bd[tid]; sBr[tid] = br[tid]; }

    for (int e = tid; e < KTAP*128; e += 256){
        int tap = e>>7, n = e&127;
        int hh = n>>6, w = n&63;
        int h = h0 + hh;
        int kt = tap/9, rr = tap-kt*9, kh = rr/3, kw = rr-kh*3;
        int t_in = t-1+kt;
        bool t_ok = (unsigned)t_in < TT;
        int t_c = min(max(t_in,0),TT-1);
        int pidx = t*HWX + h*WWD + w;
        float dh = g_off[(2*tap)*PLANE + pidx];
        float dw = g_off[(2*tap+1)*PLANE + pidx];
        float h_s = (float)(h-1+kh)+dh, w_s = (float)(w-1+kw)+dw;
        float h0f = floorf(h_s), w0f = floorf(w_s);
        float fh = h_s-h0f, fw = w_s-w0f;
        int hb = (int)h0f, wb = (int)w0f;
        unsigned mask = 0;
        if (t_ok){
            unsigned h0ok = ((unsigned)hb < HH),  h1ok = ((unsigned)(hb+1) < HH);
            unsigned w0ok = ((unsigned)wb < WWD), w1ok = ((unsigned)(wb+1) < WWD);
            mask = (h0ok&w0ok) | ((h0ok&w1ok)<<1) | ((h1ok&w0ok)<<2) | ((h1ok&w1ok)<<3);
        }
        int hbc = min(max(hb,-2),64), wbc = min(max(wb,-2),64);
        uint32_t pack = (uint32_t)(wbc+2) | ((uint32_t)(hbc+2)<<7) | ((uint32_t)t_c<<14) | (mask<<17);
        __half2 f2 = __floats2half2_rn(fh, fw);
        sTab[e] = make_uint2(pack, *(uint32_t*)&f2);
    }
    __syncthreads();

    int m0 = (wid&3)*32, n0 = (wid>>2)*32;
    int base_p = t*HWX + h0*WWD;
    float acc[8][4];
    #pragma unroll
    for (int i=0;i<8;i++){ acc[i][0]=0.f; acc[i][1]=0.f; acc[i][2]=0.f; acc[i][3]=0.f; }

    int o_w = tid>>2, part = tid&3, s0w = part*2;

    {
        uint4 P[2][4]; float W[2][4];
        dledg(0, tid, sTab, P, W, 0); dlsts(SA0, tid, P, W, 0);
        dledg(0, tid, sTab, P, W, 2); dlsts(SA0, tid, P, W, 2);
        const uint4* sp = (const uint4*)(g_Wdh + o_w*64 + part*16);
        uint4 wv0 = sp[0], wv1 = sp[1];
        *(uint4*)(SB0 + o_w*128 + ((s0w ^ (o_w&7))<<4)) = wv0;
        *(uint4*)(SB0 + o_w*128 + (((s0w+1)^(o_w&7))<<4)) = wv1;
    }
    __syncthreads();

    int q = lane>>2, c2 = (lane&3)<<1;
    for (int it = 0; it < 28; it++){
        int p = it & 1;
        uint32_t Ab = sbase + (p ? 17408 : 1024);
        uint32_t Bb = sbase + (p ? 41984 : 33792);
        char* SAn = p ? SA0 : SA1;
        char* SBn = p ? SB0 : SB1;
        int nxt = it + 1;
        bool more = nxt < 28;

        uint4 P[2][4]; float W[2][4];
        uint4 wv0, wv1;
        if (more){
            if (nxt < 27) dledg(nxt, tid, sTab, P, W, 0);
            else          rledg(tid, base_p, P, W, 0);
            const __half* Wsrc = (nxt < 27) ? (g_Wdh + nxt*4096) : g_Wrh;
            const uint4* sp = (const uint4*)(Wsrc + o_w*64 + part*16);
            wv0 = sp[0]; wv1 = sp[1];
        }
        gemm_half<0>(Ab, Bb, m0, n0, lane, acc);
        if (more){
            dlsts(SAn, tid, P, W, 0);
            if (nxt < 27) dledg(nxt, tid, sTab, P, W, 2);
            else          rledg(tid, base_p, P, W, 2);
        }
        gemm_half<2>(Ab, Bb, m0, n0, lane, acc);
        if (more){
            dlsts(SAn, tid, P, W, 2);
            *(uint4*)(SBn + o_w*128 + ((s0w ^ (o_w&7))<<4)) = wv0;
            *(uint4*)(SBn + o_w*128 + (((s0w+1)^(o_w&7))<<4)) = wv1;
        }
        if (it == 26){
            #pragma unroll
            for (int t8=0;t8<8;t8++){
                int ni=(t8>>1)&1, hn=t8&1;
                int o = n0 + ni*16 + hn*8 + c2;
                float b0v = sBd[o], b1v = sBd[o+1];
                float v;
                v = acc[t8][0]+b0v; acc[t8][0] = v>=0.f?v:0.01f*v;
                v = acc[t8][1]+b1v; acc[t8][1] = v>=0.f?v:0.01f*v;
                v = acc[t8][2]+b0v; acc[t8][2] = v>=0.f?v:0.01f*v;
                v = acc[t8][3]+b1v; acc[t8][3] = v>=0.f?v:0.01f*v;
            }
        }
        __syncthreads();
    }

    float* sOut = (float*)(sm + 1024);  // [o][132]
    #pragma unroll
    for (int t8=0;t8<8;t8++){
        int mi=t8>>2, ni=(t8>>1)&1, hn=t8&1;
        int o = n0 + ni*16 + hn*8 + c2;
        int nn = m0 + mi*16 + q;
        float b0v = sBr[o], b1v = sBr[o+1];
        sOut[o*132+nn]       = acc[t8][0]+b0v;
        sOut[(o+1)*132+nn]   = acc[t8][1]+b1v;
        sOut[o*132+nn+8]     = acc[t8][2]+b0v;
        sOut[(o+1)*132+nn+8] = acc[t8][3]+b1v;
    }
    __syncthreads();
    int n4 = (tid&31)*4;
    #pragma unroll
    for (int i=0;i<8;i++){
        int o = (tid>>5) + i*8;
        float4 v = *(float4*)&sOut[o*132+n4];
        *(float4*)&out[o*PLANE + base_p + n4] = v;
    }
}

// -------- launch --------
extern "C" void kernel_launch(void* const* d_in, const int* in_sizes, int n_in,
                              void* d_out, int out_size) {
    (void)in_sizes; (void)n_in; (void)out_size;
    const float* x    = (const float*)d_in[0];
    const float* W1   = (const float*)d_in[1];
    const float* b1   = (const float*)d_in[2];
    const float* Woff = (const float*)d_in[3];
    const float* boff = (const float*)d_in[4];
    const float* Wd   = (const float*)d_in[5];
    const float* bd   = (const float*)d_in[6];
    const float* Wr   = (const float*)d_in[7];
    const float* br   = (const float*)d_in[8];
    float* out = (float*)d_out;

    cudaFuncSetAttribute(conv_f16<0>, cudaFuncAttributeMaxDynamicSharedMemorySize, SMEM_CONV);
    cudaFuncSetAttribute(conv_f16<1>, cudaFuncAttributeMaxDynamicSharedMemorySize, SMEM_CONV);
    cudaFuncSetAttribute(deform_f16,  cudaFuncAttributeMaxDynamicSharedMemorySize, SMEM_DEF);

    prep_weights<<<(KTAP*64*64 + 255)/256, 256>>>(W1, Woff, Wd, Wr);
    prep_x<<<256, 256>>>(x);
    conv_f16<0><<<256, 256, SMEM_CONV>>>(b1);
    conv_f16<1><<<256, 256, SMEM_CONV>>>(boff);
    deform_f16<<<256, 256, SMEM_DEF>>>(bd, br, out);
}

// round 10
// speedup vs baseline: 1.4201x; 1.0673x over previous
#include <cuda_runtime.h>
#include <cuda_fp16.h>
#include <cstdint>

#define TT 8
#define HH 64
#define WWD 64
#define HWX 4096
#define PLANE 32768
#define KTAP 27

// -------- device scratch --------
__device__ __half g_xh[64*PLANE];        // x fp16, [pos][c]
__device__ __half g_y1h[64*PLANE];       // lrelu(conv1) fp16, [pos][c]
__device__ float  g_off[54*PLANE];       // offsets fp32, [o][pos]
__device__ __half g_W1h[KTAP*64*64];     // [tap][o][c]
__device__ __half g_Woffh[KTAP*64*64];
__device__ __half g_Wdh[KTAP*64*64];
__device__ __half g_Wrh[64*64];          // [o][c]

__device__ __forceinline__ uint32_t smem_u32(const void* p){
    uint32_t a;
    asm("{ .reg .u64 t; cvta.to.shared.u64 t, %1; cvt.u32.u64 %0, t; }"
        : "=r"(a) : "l"(p));
    return a;
}
__device__ __forceinline__ void ldsm4(uint32_t& r0,uint32_t& r1,uint32_t& r2,uint32_t& r3, uint32_t addr){
    asm volatile("ldmatrix.sync.aligned.m8n8.x4.shared.b16 {%0,%1,%2,%3}, [%4];"
        : "=r"(r0),"=r"(r1),"=r"(r2),"=r"(r3) : "r"(addr));
}
__device__ __forceinline__ void mma16816(float* d, uint32_t a0,uint32_t a1,uint32_t a2,uint32_t a3,
                                         uint32_t b0,uint32_t b1){
    asm volatile("mma.sync.aligned.m16n8k16.row.col.f32.f16.f16.f32 "
        "{%0,%1,%2,%3},{%4,%5,%6,%7},{%8,%9},{%0,%1,%2,%3};"
        : "+f"(d[0]),"+f"(d[1]),"+f"(d[2]),"+f"(d[3])
        : "r"(a0),"r"(a1),"r"(a2),"r"(a3),"r"(b0),"r"(b1));
}

// ---- conv gemm: full K=64 tap, A straight from window (row offset woff), B from slot ----
__device__ __forceinline__ void gemm_conv(uint32_t WinB, int woff, uint32_t Bb, int n0,
                                          int lane, float acc[8][4]){
    int g = lane>>3, r = lane&7;
    #pragma unroll
    for (int st=0; st<4; st++){
        uint32_t a[2][4], b[2][4];
        #pragma unroll
        for (int mi=0;mi<2;mi++){
            int rowA = woff + mi*16 + (g&1)*8 + r;
            int segA = st*2 + (g>>1);
            ldsm4(a[mi][0],a[mi][1],a[mi][2],a[mi][3],
                  WinB + rowA*128 + ((segA ^ (rowA&7))<<4));
        }
        #pragma unroll
        for (int ni=0;ni<2;ni++){
            int rowB = n0 + ni*16 + (g>>1)*8 + r;
            int segB = st*2 + (g&1);
            ldsm4(b[ni][0],b[ni][1],b[ni][2],b[ni][3],
                  Bb + rowB*128 + ((segB ^ (rowB&7))<<4));
        }
        #pragma unroll
        for (int mi=0;mi<2;mi++)
        #pragma unroll
        for (int ni=0;ni<2;ni++){
            mma16816(acc[mi*4+ni*2],   a[mi][0],a[mi][1],a[mi][2],a[mi][3], b[ni][0],b[ni][1]);
            mma16816(acc[mi*4+ni*2+1], a[mi][0],a[mi][1],a[mi][2],a[mi][3], b[ni][2],b[ni][3]);
        }
    }
}

// ---- deform gemm half-chunk (2 of 4 stages), both tiles staged ----
template<int ST0>
__device__ __forceinline__ void gemm_half(uint32_t Ab, uint32_t Bb, int m0, int n0,
                                          int lane, float acc[8][4]){
    int g = lane>>3, r = lane&7;
    #pragma unroll
    for (int s=0;s<2;s++){
        int st = ST0 + s;
        uint32_t a[2][4], b[2][4];
        #pragma unroll
        for (int mi=0;mi<2;mi++){
            int rowA = m0 + mi*16 + (g&1)*8 + r;
            int segA = st*2 + (g>>1);
            ldsm4(a[mi][0],a[mi][1],a[mi][2],a[mi][3],
                  Ab + rowA*128 + ((segA ^ (rowA&7))<<4));
        }
        #pragma unroll
        for (int ni=0;ni<2;ni++){
            int rowB = n0 + ni*16 + (g>>1)*8 + r;
            int segB = st*2 + (g&1);
            ldsm4(b[ni][0],b[ni][1],b[ni][2],b[ni][3],
                  Bb + rowB*128 + ((segB ^ (rowB&7))<<4));
        }
        #pragma unroll
        for (int mi=0;mi<2;mi++)
        #pragma unroll
        for (int ni=0;ni<2;ni++){
            mma16816(acc[mi*4+ni*2],   a[mi][0],a[mi][1],a[mi][2],a[mi][3], b[ni][0],b[ni][1]);
            mma16816(acc[mi*4+ni*2+1], a[mi][0],a[mi][1],a[mi][2],a[mi][3], b[ni][2],b[ni][3]);
        }
    }
}

__device__ __forceinline__ uint4 bilin8(const uint4* P, const float* W){
    uint4 r;
    const uint32_t* p0 = (const uint32_t*)&P[0];
    const uint32_t* p1 = (const uint32_t*)&P[1];
    const uint32_t* p2 = (const uint32_t*)&P[2];
    const uint32_t* p3 = (const uint32_t*)&P[3];
    uint32_t* ro = (uint32_t*)&r;
    #pragma unroll
    for (int k=0;k<4;k++){
        float2 f0 = __half22float2(*(const __half2*)&p0[k]);
        float2 f1 = __half22float2(*(const __half2*)&p1[k]);
        float2 f2 = __half22float2(*(const __half2*)&p2[k]);
        float2 f3 = __half22float2(*(const __half2*)&p3[k]);
        float vx = W[0]*f0.x + W[1]*f1.x + W[2]*f2.x + W[3]*f3.x;
        float vy = W[0]*f0.y + W[1]*f1.y + W[2]*f2.y + W[3]*f3.y;
        __half2 h = __floats2half2_rn(vx, vy);
        ro[k] = *(uint32_t*)&h;
    }
    return r;
}

// -------- fused prep: blocks [0,432) repack weights; [432,688) transpose x --------
__global__ void prep_all(const float* __restrict__ W1, const float* __restrict__ Woff,
                         const float* __restrict__ Wd, const float* __restrict__ Wr,
                         const float* __restrict__ x){
    __shared__ __half sT[128*72];
    int tid = threadIdx.x;
    if (blockIdx.x < 432){
        int i = blockIdx.x*256 + tid;
        if (i < KTAP*64*64){
            int tap = i>>12, o = (i>>6)&63, c = i&63;
            int src = o*1728 + c*27 + tap;
            g_W1h[i] = __float2half(W1[src]);
            g_Wdh[i] = __float2half(Wd[src]);
            g_Woffh[i] = (o < 54) ? __float2half(Woff[src]) : __half(0.f);
            if (i < 64*64) g_Wrh[i] = __float2half(Wr[i]);
        }
    } else {
        int pos0 = (blockIdx.x - 432)*128;
        int p = tid & 127, ch0 = tid >> 7;
        #pragma unroll 8
        for (int cc = 0; cc < 32; cc++){
            int c = cc*2 + ch0;
            sT[p*72 + c] = __float2half(x[c*PLANE + pos0 + p]);
        }
        __syncthreads();
        int oc = tid & 7;
        #pragma unroll
        for (int j = 0; j < 4; j++){
            int n = (tid>>3) + j*32;
            uint4 v = *(uint4*)&sT[n*72 + oc*8];
            *(uint4*)&g_xh[(pos0+n)*64 + oc*8] = v;
        }
    }
}

// ==================== conv 3x3x3: window + 9 B-slots per kt, 2 syncs/kt ====================
// smem: misc[0,1024) | WIN@1024 (33792) | B slots @34816 (9*8192=73728) end 108544
// epilogue aliases @1024
#define SMEM_CONV 108544
template<int MODE>   // 0: xh -> y1h (lrelu); 1: y1h -> g_off (54 ch)
__global__ void __launch_bounds__(256)
conv_f16(const float* __restrict__ bias)
{
    extern __shared__ char sm[];
    float* sBias = (float*)sm;
    char* WIN = sm + 1024;
    char* SB  = sm + 34816;
    uint32_t sbase = smem_u32(sm);
    uint32_t WinB = sbase + 1024;
    uint32_t Bb0  = sbase + 34816;
    const __half* src  = (MODE==0)? g_xh  : g_y1h;
    const __half* Wall = (MODE==0)? g_W1h : g_Woffh;

    int tid = threadIdx.x, lane = tid&31, wid = tid>>5;
    int t = blockIdx.x>>5, h0 = (blockIdx.x&31)<<1;
    if (tid < 64) sBias[tid] = (MODE==0 || tid<54)? bias[tid] : 0.f;

    int o_w = tid>>2, part = tid&3, s0w = part*2;
    int m0 = (wid&3)*32, n0 = (wid>>2)*32;
    float acc[8][4];
    #pragma unroll
    for (int i=0;i<8;i++){ acc[i][0]=0.f; acc[i][1]=0.f; acc[i][2]=0.f; acc[i][3]=0.f; }

    int whh = (m0>>6)*66 + (m0&63);   // warp-constant window row base

    for (int kt=0; kt<3; kt++){
        int t_in = t-1+kt;
        bool tok = (unsigned)t_in < TT;
        if (kt) __syncthreads();          // everyone done reading previous window + B
        // window [4h][66w][64c], swizzled, zero halo
        for (int e = tid; e < 2112; e += 256){
            int pos = e >> 3, seg = e & 7;
            int hr = pos/66, wc = pos - hr*66;
            int h_in = h0 + hr - 1, w_in = wc - 1;
            uint4 v = make_uint4(0,0,0,0);
            if (tok && (unsigned)h_in < HH && (unsigned)w_in < WWD)
                v = *(const uint4*)&src[(t_in*HWX + h_in*WWD + w_in)*64 + seg*8];
            *(uint4*)(WIN + pos*128 + ((seg ^ (pos&7))<<4)) = v;
        }
        // all 9 B tiles of this kt phase
        #pragma unroll
        for (int j=0;j<9;j++){
            const uint4* sp = (const uint4*)(Wall + (kt*9+j)*4096 + o_w*64 + part*16);
            uint4 v0 = sp[0], v1 = sp[1];
            char* SBj = SB + j*8192;
            *(uint4*)(SBj + o_w*128 + ((s0w ^ (o_w&7))<<4)) = v0;
            *(uint4*)(SBj + o_w*128 + (((s0w+1)^(o_w&7))<<4)) = v1;
        }
        __syncthreads();
        // 9 sync-free gemms
        #pragma unroll
        for (int j=0;j<9;j++){
            int kh = j/3, kw = j - kh*3;
            gemm_conv(WinB, whh + kh*66 + kw, Bb0 + j*8192, n0, lane, acc);
        }
    }
    __syncthreads();

    int q = lane>>2, c2 = (lane&3)<<1;
    int base = t*HWX + h0*WWD;
    int oc = tid&7;
    if (MODE==0){
        uint32_t* sOutH2 = (uint32_t*)(sm + 1024);  // [pos][36] half2
        #pragma unroll
        for (int t8=0;t8<8;t8++){
            int mi=t8>>2, ni=(t8>>1)&1, hn=t8&1;
            int o = n0 + ni*16 + hn*8 + c2;
            int r0 = m0 + mi*16 + q;
            float b0v = sBias[o], b1v = sBias[o+1];
            float v0 = acc[t8][0]+b0v, v1 = acc[t8][1]+b1v;
            float v2 = acc[t8][2]+b0v, v3 = acc[t8][3]+b1v;
            v0 = v0>=0.f?v0:0.01f*v0; v1 = v1>=0.f?v1:0.01f*v1;
            v2 = v2>=0.f?v2:0.01f*v2; v3 = v3>=0.f?v3:0.01f*v3;
            __half2 h01 = __floats2half2_rn(v0,v1);
            __half2 h23 = __floats2half2_rn(v2,v3);
            sOutH2[r0*36     + (o>>1)] = *(uint32_t*)&h01;
            sOutH2[(r0+8)*36 + (o>>1)] = *(uint32_t*)&h23;
        }
        __syncthreads();
        __half* sOutH = (__half*)(sm + 1024);
        #pragma unroll
        for (int jj=0;jj<4;jj++){
            int n = (tid>>3) + jj*32;
            uint4 v = *(uint4*)&sOutH[n*72 + oc*8];
            *(uint4*)&g_y1h[(base+n)*64 + oc*8] = v;
        }
    } else {
        float* sOut = (float*)(sm + 1024);   // [o][132]
        #pragma unroll
        for (int t8=0;t8<8;t8++){
            int mi=t8>>2, ni=(t8>>1)&1, hn=t8&1;
            int o = n0 + ni*16 + hn*8 + c2;
            int nn = m0 + mi*16 + q;
            float b0v = sBias[o], b1v = sBias[o+1];
            sOut[o*132+nn]       = acc[t8][0]+b0v;
            sOut[(o+1)*132+nn]   = acc[t8][1]+b1v;
            sOut[o*132+nn+8]     = acc[t8][2]+b0v;
            sOut[(o+1)*132+nn+8] = acc[t8][3]+b1v;
        }
        __syncthreads();
        int n4 = (tid&31)*4;
        #pragma unroll
        for (int i=0;i<8;i++){
            int o = (tid>>5) + i*8;
            if (o < 54){
                float4 v = *(float4*)&sOut[o*132+n4];
                *(float4*)&g_off[o*PLANE + base + n4] = v;
            }
        }
    }
}

// ==================== deformable conv + residual + lrelu (R9 structure) ====================
// smem: misc[0,1024) | SA0@1024 SA1@17408 SB0@33792 SB1@41984 | tab@50176 (27648) end 77824
#define SMEM_DEF 77824

__device__ __forceinline__ void dledg(int tap, int tid, const uint2* sTab,
                                      uint4 P[2][4], float W[2][4], int j0){
    int oc = tid&7;
    #pragma unroll
    for (int jj=0;jj<2;jj++){
        int n = (tid>>3) + (j0+jj)*32;
        uint2 tb = sTab[tap*128 + n];
        uint32_t pk = tb.x;
        __half2 fhw = *(__half2*)&tb.y;
        float fh = __low2float(fhw), fw = __high2float(fhw);
        int wb = (int)(pk&127)-2, hb = (int)((pk>>7)&127)-2;
        int tc = (int)((pk>>14)&7);
        unsigned mask = pk>>17;
        float w00=(1.f-fh)*(1.f-fw), w01=(1.f-fh)*fw, w10=fh*(1.f-fw), w11=fh*fw;
        if(!(mask&1u)) w00=0.f;
        if(!(mask&2u)) w01=0.f;
        if(!(mask&4u)) w10=0.f;
        if(!(mask&8u)) w11=0.f;
        int ih0=min(max(hb,0),HH-1),  ih1=min(max(hb+1,0),HH-1);
        int iw0=min(max(wb,0),WWD-1), iw1=min(max(wb+1,0),WWD-1);
        int b0 = tc*HWX;
        P[jj][0] = *(const uint4*)&g_y1h[(b0+ih0*WWD+iw0)*64 + oc*8];
        P[jj][1] = *(const uint4*)&g_y1h[(b0+ih0*WWD+iw1)*64 + oc*8];
        P[jj][2] = *(const uint4*)&g_y1h[(b0+ih1*WWD+iw0)*64 + oc*8];
        P[jj][3] = *(const uint4*)&g_y1h[(b0+ih1*WWD+iw1)*64 + oc*8];
        W[jj][0]=w00; W[jj][1]=w01; W[jj][2]=w10; W[jj][3]=w11;
    }
}
__device__ __forceinline__ void rledg(int tid, int base_p, uint4 P[2][4], float W[2][4], int j0){
    int oc = tid&7;
    #pragma unroll
    for (int jj=0;jj<2;jj++){
        int n = (tid>>3) + (j0+jj)*32;
        P[jj][0] = *(const uint4*)&g_xh[(base_p+n)*64 + oc*8];
        P[jj][1] = make_uint4(0,0,0,0);
        P[jj][2] = make_uint4(0,0,0,0);
        P[jj][3] = make_uint4(0,0,0,0);
        W[jj][0]=1.f; W[jj][1]=0.f; W[jj][2]=0.f; W[jj][3]=0.f;
    }
}
__device__ __forceinline__ void dlsts(char* SA, int tid, uint4 P[2][4], float W[2][4], int j0){
    int oc = tid&7;
    #pragma unroll
    for (int jj=0;jj<2;jj++){
        int n = (tid>>3) + (j0+jj)*32;
        uint4 r = bilin8(P[jj], W[jj]);
        *(uint4*)(SA + n*128 + ((oc ^ (n&7))<<4)) = r;
    }
}

__global__ void __launch_bounds__(256)
deform_f16(const float* __restrict__ bd, const float* __restrict__ br,
           float* __restrict__ out)
{
    extern __shared__ char sm[];
    float* sBd = (float*)sm;
    float* sBr = (float*)(sm + 256);
    char* SA0 = sm + 1024;
    char* SA1 = sm + 17408;
    char* SB0 = sm + 33792;
    char* SB1 = sm + 41984;
    uint2* sTab = (uint2*)(sm + 50176);
    uint32_t sbase = smem_u32(sm);

    int tid = threadIdx.x, lane = tid&31, wid = tid>>5;
    int t = blockIdx.x>>5, h0 = (blockIdx.x&31)<<1;
    if (tid < 64){ sBd[tid] = bd[tid]; sBr[tid] = br[tid]; }

    for (int e = tid; e < KTAP*128; e += 256){
        int tap = e>>7, n = e&127;
        int hh = n>>6, w = n&63;
        int h = h0 + hh;
        int kt = tap/9, rr = tap-kt*9, kh = rr/3, kw = rr-kh*3;
        int t_in = t-1+kt;
        bool t_ok = (unsigned)t_in < TT;
        int t_c = min(max(t_in,0),TT-1);
        int pidx = t*HWX + h*WWD + w;
        float dh = g_off[(2*tap)*PLANE + pidx];
        float dw = g_off[(2*tap+1)*PLANE + pidx];
        float h_s = (float)(h-1+kh)+dh, w_s = (float)(w-1+kw)+dw;
        float h0f = floorf(h_s), w0f = floorf(w_s);
        float fh = h_s-h0f, fw = w_s-w0f;
        int hb = (int)h0f, wb = (int)w0f;
        unsigned mask = 0;
        if (t_ok){
            unsigned h0ok = ((unsigned)hb < HH),  h1ok = ((unsigned)(hb+1) < HH);
            unsigned w0ok = ((unsigned)wb < WWD), w1ok = ((unsigned)(wb+1) < WWD);
            mask = (h0ok&w0ok) | ((h0ok&w1ok)<<1) | ((h1ok&w0ok)<<2) | ((h1ok&w1ok)<<3);
        }
        int hbc = min(max(hb,-2),64), wbc = min(max(wb,-2),64);
        uint32_t pack = (uint32_t)(wbc+2) | ((uint32_t)(hbc+2)<<7) | ((uint32_t)t_c<<14) | (mask<<17);
        __half2 f2 = __floats2half2_rn(fh, fw);
        sTab[e] = make_uint2(pack, *(uint32_t*)&f2);
    }
    __syncthreads();

    int m0 = (wid&3)*32, n0 = (wid>>2)*32;
    int base_p = t*HWX + h0*WWD;
    float acc[8][4];
    #pragma unroll
    for (int i=0;i<8;i++){ acc[i][0]=0.f; acc[i][1]=0.f; acc[i][2]=0.f; acc[i][3]=0.f; }

    int o_w = tid>>2, part = tid&3, s0w = part*2;

    {
        uint4 P[2][4]; float W[2][4];
        dledg(0, tid, sTab, P, W, 0); dlsts(SA0, tid, P, W, 0);
        dledg(0, tid, sTab, P, W, 2); dlsts(SA0, tid, P, W, 2);
        const uint4* sp = (const uint4*)(g_Wdh + o_w*64 + part*16);
        uint4 wv0 = sp[0], wv1 = sp[1];
        *(uint4*)(SB0 + o_w*128 + ((s0w ^ (o_w&7))<<4)) = wv0;
        *(uint4*)(SB0 + o_w*128 + (((s0w+1)^(o_w&7))<<4)) = wv1;
    }
    __syncthreads();

    int q = lane>>2, c2 = (lane&3)<<1;
    for (int it = 0; it < 28; it++){
        int p = it & 1;
        uint32_t Ab = sbase + (p ? 17408 : 1024);
        uint32_t Bb = sbase + (p ? 41984 : 33792);
        char* SAn = p ? SA0 : SA1;
        char* SBn = p ? SB0 : SB1;
        int nxt = it + 1;
        bool more = nxt < 28;

        uint4 P[2][4]; float W[2][4];
        uint4 wv0, wv1;
        if (more){
            if (nxt < 27) dledg(nxt, tid, sTab, P, W, 0);
            else          rledg(tid, base_p, P, W, 0);
            const __half* Wsrc = (nxt < 27) ? (g_Wdh + nxt*4096) : g_Wrh;
            const uint4* sp = (const uint4*)(Wsrc + o_w*64 + part*16);
            wv0 = sp[0]; wv1 = sp[1];
        }
        gemm_half<0>(Ab, Bb, m0, n0, lane, acc);
        if (more){
            dlsts(SAn, tid, P, W, 0);
            if (nxt < 27) dledg(nxt, tid, sTab, P, W, 2);
            else          rledg(tid, base_p, P, W, 2);
        }
        gemm_half<2>(Ab, Bb, m0, n0, lane, acc);
        if (more){
            dlsts(SAn, tid, P, W, 2);
            *(uint4*)(SBn + o_w*128 + ((s0w ^ (o_w&7))<<4)) = wv0;
            *(uint4*)(SBn + o_w*128 + (((s0w+1)^(o_w&7))<<4)) = wv1;
        }
        if (it == 26){
            #pragma unroll
            for (int t8=0;t8<8;t8++){
                int ni=(t8>>1)&1, hn=t8&1;
                int o = n0 + ni*16 + hn*8 + c2;
                float b0v = sBd[o], b1v = sBd[o+1];
                float v;
                v = acc[t8][0]+b0v; acc[t8][0] = v>=0.f?v:0.01f*v;
                v = acc[t8][1]+b1v; acc[t8][1] = v>=0.f?v:0.01f*v;
                v = acc[t8][2]+b0v; acc[t8][2] = v>=0.f?v:0.01f*v;
                v = acc[t8][3]+b1v; acc[t8][3] = v>=0.f?v:0.01f*v;
            }
        }
        __syncthreads();
    }

    float* sOut = (float*)(sm + 1024);  // [o][132]
    #pragma unroll
    for (int t8=0;t8<8;t8++){
        int mi=t8>>2, ni=(t8>>1)&1, hn=t8&1;
        int o = n0 + ni*16 + hn*8 + c2;
        int nn = m0 + mi*16 + q;
        float b0v = sBr[o], b1v = sBr[o+1];
        sOut[o*132+nn]       = acc[t8][0]+b0v;
        sOut[(o+1)*132+nn]   = acc[t8][1]+b1v;
        sOut[o*132+nn+8]     = acc[t8][2]+b0v;
        sOut[(o+1)*132+nn+8] = acc[t8][3]+b1v;
    }
    __syncthreads();
    int n4 = (tid&31)*4;
    #pragma unroll
    for (int i=0;i<8;i++){
        int o = (tid>>5) + i*8;
        float4 v = *(float4*)&sOut[o*132+n4];
        *(float4*)&out[o*PLANE + base_p + n4] = v;
    }
}

// -------- launch --------
extern "C" void kernel_launch(void* const* d_in, const int* in_sizes, int n_in,
                              void* d_out, int out_size) {
    (void)in_sizes; (void)n_in; (void)out_size;
    const float* x    = (const float*)d_in[0];
    const float* W1   = (const float*)d_in[1];
    const float* b1   = (const float*)d_in[2];
    const float* Woff = (const float*)d_in[3];
    const float* boff = (const float*)d_in[4];
    const float* Wd   = (const float*)d_in[5];
    const float* bd   = (const float*)d_in[6];
    const float* Wr   = (const float*)d_in[7];
    const float* br   = (const float*)d_in[8];
    float* out = (float*)d_out;

    cudaFuncSetAttribute(conv_f16<0>, cudaFuncAttributeMaxDynamicSharedMemorySize, SMEM_CONV);
    cudaFuncSetAttribute(conv_f16<1>, cudaFuncAttributeMaxDynamicSharedMemorySize, SMEM_CONV);
    cudaFuncSetAttribute(deform_f16,  cudaFuncAttributeMaxDynamicSharedMemorySize, SMEM_DEF);

    prep_all<<<688, 256>>>(W1, Woff, Wd, Wr, x);
    conv_f16<0><<<256, 256, SMEM_CONV>>>(b1);
    conv_f16<1><<<256, 256, SMEM_CONV>>>(boff);
    deform_f16<<<256, 256, SMEM_DEF>>>(bd, br, out);
}

// round 11
// speedup vs baseline: 1.6174x; 1.1389x over previous
#include <cuda_runtime.h>
#include <cuda_fp16.h>
#include <cstdint>

#define TT 8
#define HH 64
#define WWD 64
#define HWX 4096
#define PLANE 32768
#define KTAP 27

// -------- device scratch --------
__device__ __half g_xh[64*PLANE];        // x fp16, [pos][c]
__device__ __half g_y1h[64*PLANE];       // lrelu(conv1) fp16, [pos][c]
__device__ float  g_off[54*PLANE];       // offsets fp32, [o][pos]
__device__ __half g_W1h[KTAP*64*64];     // [tap][o][c]
__device__ __half g_Woffh[KTAP*64*64];
__device__ __half g_Wdh[KTAP*64*64];
__device__ __half g_Wrh[64*64];          // [o][c]

__device__ __forceinline__ uint32_t smem_u32(const void* p){
    uint32_t a;
    asm("{ .reg .u64 t; cvta.to.shared.u64 t, %1; cvt.u32.u64 %0, t; }"
        : "=r"(a) : "l"(p));
    return a;
}
__device__ __forceinline__ void ldsm4(uint32_t& r0,uint32_t& r1,uint32_t& r2,uint32_t& r3, uint32_t addr){
    asm volatile("ldmatrix.sync.aligned.m8n8.x4.shared.b16 {%0,%1,%2,%3}, [%4];"
        : "=r"(r0),"=r"(r1),"=r"(r2),"=r"(r3) : "r"(addr));
}
__device__ __forceinline__ void mma16816(float* d, uint32_t a0,uint32_t a1,uint32_t a2,uint32_t a3,
                                         uint32_t b0,uint32_t b1){
    asm volatile("mma.sync.aligned.m16n8k16.row.col.f32.f16.f16.f32 "
        "{%0,%1,%2,%3},{%4,%5,%6,%7},{%8,%9},{%0,%1,%2,%3};"
        : "+f"(d[0]),"+f"(d[1]),"+f"(d[2]),"+f"(d[3])
        : "r"(a0),"r"(a1),"r"(a2),"r"(a3),"r"(b0),"r"(b1));
}

// ---- conv gemm: full K=64 tap, A straight from window (row offset woff), B from slot ----
__device__ __forceinline__ void gemm_conv(uint32_t WinB, int woff, uint32_t Bb, int n0,
                                          int lane, float acc[8][4]){
    int g = lane>>3, r = lane&7;
    #pragma unroll
    for (int st=0; st<4; st++){
        uint32_t a[2][4], b[2][4];
        #pragma unroll
        for (int mi=0;mi<2;mi++){
            int rowA = woff + mi*16 + (g&1)*8 + r;
            int segA = st*2 + (g>>1);
            ldsm4(a[mi][0],a[mi][1],a[mi][2],a[mi][3],
                  WinB + rowA*128 + ((segA ^ (rowA&7))<<4));
        }
        #pragma unroll
        for (int ni=0;ni<2;ni++){
            int rowB = n0 + ni*16 + (g>>1)*8 + r;
            int segB = st*2 + (g&1);
            ldsm4(b[ni][0],b[ni][1],b[ni][2],b[ni][3],
                  Bb + rowB*128 + ((segB ^ (rowB&7))<<4));
        }
        #pragma unroll
        for (int mi=0;mi<2;mi++)
        #pragma unroll
        for (int ni=0;ni<2;ni++){
            mma16816(acc[mi*4+ni*2],   a[mi][0],a[mi][1],a[mi][2],a[mi][3], b[ni][0],b[ni][1]);
            mma16816(acc[mi*4+ni*2+1], a[mi][0],a[mi][1],a[mi][2],a[mi][3], b[ni][2],b[ni][3]);
        }
    }
}

// ---- deform gemm half-chunk (2 of 4 stages), both tiles staged ----
template<int ST0>
__device__ __forceinline__ void gemm_half(uint32_t Ab, uint32_t Bb, int m0, int n0,
                                          int lane, float acc[8][4]){
    int g = lane>>3, r = lane&7;
    #pragma unroll
    for (int s=0;s<2;s++){
        int st = ST0 + s;
        uint32_t a[2][4], b[2][4];
        #pragma unroll
        for (int mi=0;mi<2;mi++){
            int rowA = m0 + mi*16 + (g&1)*8 + r;
            int segA = st*2 + (g>>1);
            ldsm4(a[mi][0],a[mi][1],a[mi][2],a[mi][3],
                  Ab + rowA*128 + ((segA ^ (rowA&7))<<4));
        }
        #pragma unroll
        for (int ni=0;ni<2;ni++){
            int rowB = n0 + ni*16 + (g>>1)*8 + r;
            int segB = st*2 + (g&1);
            ldsm4(b[ni][0],b[ni][1],b[ni][2],b[ni][3],
                  Bb + rowB*128 + ((segB ^ (rowB&7))<<4));
        }
        #pragma unroll
        for (int mi=0;mi<2;mi++)
        #pragma unroll
        for (int ni=0;ni<2;ni++){
            mma16816(acc[mi*4+ni*2],   a[mi][0],a[mi][1],a[mi][2],a[mi][3], b[ni][0],b[ni][1]);
            mma16816(acc[mi*4+ni*2+1], a[mi][0],a[mi][1],a[mi][2],a[mi][3], b[ni][2],b[ni][3]);
        }
    }
}

// half2 bilinear combine: 4 taps x 8 channels, all fp16
__device__ __forceinline__ uint4 bilinH(const uint4* P, uint2 wpack){
    __half2 w01 = *(__half2*)&wpack.x;
    __half2 w23 = *(__half2*)&wpack.y;
    __half2 w00b = __low2half2(w01), w01b = __high2half2(w01);
    __half2 w10b = __low2half2(w23), w11b = __high2half2(w23);
    const uint32_t* p0 = (const uint32_t*)&P[0];
    const uint32_t* p1 = (const uint32_t*)&P[1];
    const uint32_t* p2 = (const uint32_t*)&P[2];
    const uint32_t* p3 = (const uint32_t*)&P[3];
    uint4 r;
    uint32_t* ro = (uint32_t*)&r;
    #pragma unroll
    for (int k=0;k<4;k++){
        __half2 v = __hmul2(*(const __half2*)&p0[k], w00b);
        v = __hfma2(*(const __half2*)&p1[k], w01b, v);
        v = __hfma2(*(const __half2*)&p2[k], w10b, v);
        v = __hfma2(*(const __half2*)&p3[k], w11b, v);
        ro[k] = *(uint32_t*)&v;
    }
    return r;
}

// -------- fused prep: blocks [0,432) repack weights; [432,688) transpose x --------
__global__ void prep_all(const float* __restrict__ W1, const float* __restrict__ Woff,
                         const float* __restrict__ Wd, const float* __restrict__ Wr,
                         const float* __restrict__ x){
    __shared__ __half sT[128*72];
    int tid = threadIdx.x;
    if (blockIdx.x < 432){
        int i = blockIdx.x*256 + tid;
        if (i < KTAP*64*64){
            int tap = i>>12, o = (i>>6)&63, c = i&63;
            int src = o*1728 + c*27 + tap;
            g_W1h[i] = __float2half(W1[src]);
            g_Wdh[i] = __float2half(Wd[src]);
            g_Woffh[i] = (o < 54) ? __float2half(Woff[src]) : __half(0.f);
            if (i < 64*64) g_Wrh[i] = __float2half(Wr[i]);
        }
    } else {
        int pos0 = (blockIdx.x - 432)*128;
        int p = tid & 127, ch0 = tid >> 7;
        #pragma unroll 8
        for (int cc = 0; cc < 32; cc++){
            int c = cc*2 + ch0;
            sT[p*72 + c] = __float2half(x[c*PLANE + pos0 + p]);
        }
        __syncthreads();
        int oc = tid & 7;
        #pragma unroll
        for (int j = 0; j < 4; j++){
            int n = (tid>>3) + j*32;
            uint4 v = *(uint4*)&sT[n*72 + oc*8];
            *(uint4*)&g_xh[(pos0+n)*64 + oc*8] = v;
        }
    }
}

// ==================== conv 3x3x3: window + 9 B-slots per kt, 2 syncs/kt ====================
// smem: misc[0,1024) | WIN@1024 (33792) | B slots @34816 (9*8192=73728) end 108544
#define SMEM_CONV 108544
template<int MODE>   // 0: xh -> y1h (lrelu); 1: y1h -> g_off (54 ch)
__global__ void __launch_bounds__(256)
conv_f16(const float* __restrict__ bias)
{
    extern __shared__ char sm[];
    float* sBias = (float*)sm;
    char* WIN = sm + 1024;
    char* SB  = sm + 34816;
    uint32_t sbase = smem_u32(sm);
    uint32_t WinB = sbase + 1024;
    uint32_t Bb0  = sbase + 34816;
    const __half* src  = (MODE==0)? g_xh  : g_y1h;
    const __half* Wall = (MODE==0)? g_W1h : g_Woffh;

    int tid = threadIdx.x, lane = tid&31, wid = tid>>5;
    int t = blockIdx.x>>5, h0 = (blockIdx.x&31)<<1;
    if (tid < 64) sBias[tid] = (MODE==0 || tid<54)? bias[tid] : 0.f;

    int o_w = tid>>2, part = tid&3, s0w = part*2;
    int m0 = (wid&3)*32, n0 = (wid>>2)*32;
    float acc[8][4];
    #pragma unroll
    for (int i=0;i<8;i++){ acc[i][0]=0.f; acc[i][1]=0.f; acc[i][2]=0.f; acc[i][3]=0.f; }

    int whh = (m0>>6)*66 + (m0&63);

    for (int kt=0; kt<3; kt++){
        int t_in = t-1+kt;
        bool tok = (unsigned)t_in < TT;
        if (kt) __syncthreads();
        for (int e = tid; e < 2112; e += 256){
            int pos = e >> 3, seg = e & 7;
            int hr = pos/66, wc = pos - hr*66;
            int h_in = h0 + hr - 1, w_in = wc - 1;
            uint4 v = make_uint4(0,0,0,0);
            if (tok && (unsigned)h_in < HH && (unsigned)w_in < WWD)
                v = *(const uint4*)&src[(t_in*HWX + h_in*WWD + w_in)*64 + seg*8];
            *(uint4*)(WIN + pos*128 + ((seg ^ (pos&7))<<4)) = v;
        }
        #pragma unroll
        for (int j=0;j<9;j++){
            const uint4* sp = (const uint4*)(Wall + (kt*9+j)*4096 + o_w*64 + part*16);
            uint4 v0 = sp[0], v1 = sp[1];
            char* SBj = SB + j*8192;
            *(uint4*)(SBj + o_w*128 + ((s0w ^ (o_w&7))<<4)) = v0;
            *(uint4*)(SBj + o_w*128 + (((s0w+1)^(o_w&7))<<4)) = v1;
        }
        __syncthreads();
        #pragma unroll
        for (int j=0;j<9;j++){
            int kh = j/3, kw = j - kh*3;
            gemm_conv(WinB, whh + kh*66 + kw, Bb0 + j*8192, n0, lane, acc);
        }
    }
    __syncthreads();

    int q = lane>>2, c2 = (lane&3)<<1;
    int base = t*HWX + h0*WWD;
    int oc = tid&7;
    if (MODE==0){
        uint32_t* sOutH2 = (uint32_t*)(sm + 1024);  // [pos][36] half2
        #pragma unroll
        for (int t8=0;t8<8;t8++){
            int mi=t8>>2, ni=(t8>>1)&1, hn=t8&1;
            int o = n0 + ni*16 + hn*8 + c2;
            int r0 = m0 + mi*16 + q;
            float b0v = sBias[o], b1v = sBias[o+1];
            float v0 = acc[t8][0]+b0v, v1 = acc[t8][1]+b1v;
            float v2 = acc[t8][2]+b0v, v3 = acc[t8][3]+b1v;
            v0 = v0>=0.f?v0:0.01f*v0; v1 = v1>=0.f?v1:0.01f*v1;
            v2 = v2>=0.f?v2:0.01f*v2; v3 = v3>=0.f?v3:0.01f*v3;
            __half2 h01 = __floats2half2_rn(v0,v1);
            __half2 h23 = __floats2half2_rn(v2,v3);
            sOutH2[r0*36     + (o>>1)] = *(uint32_t*)&h01;
            sOutH2[(r0+8)*36 + (o>>1)] = *(uint32_t*)&h23;
        }
        __syncthreads();
        __half* sOutH = (__half*)(sm + 1024);
        #pragma unroll
        for (int jj=0;jj<4;jj++){
            int n = (tid>>3) + jj*32;
            uint4 v = *(uint4*)&sOutH[n*72 + oc*8];
            *(uint4*)&g_y1h[(base+n)*64 + oc*8] = v;
        }
    } else {
        float* sOut = (float*)(sm + 1024);   // [o][132]
        #pragma unroll
        for (int t8=0;t8<8;t8++){
            int mi=t8>>2, ni=(t8>>1)&1, hn=t8&1;
            int o = n0 + ni*16 + hn*8 + c2;
            int nn = m0 + mi*16 + q;
            float b0v = sBias[o], b1v = sBias[o+1];
            sOut[o*132+nn]       = acc[t8][0]+b0v;
            sOut[(o+1)*132+nn]   = acc[t8][1]+b1v;
            sOut[o*132+nn+8]     = acc[t8][2]+b0v;
            sOut[(o+1)*132+nn+8] = acc[t8][3]+b1v;
        }
        __syncthreads();
        int n4 = (tid&31)*4;
        #pragma unroll
        for (int i=0;i<8;i++){
            int o = (tid>>5) + i*8;
            if (o < 54){
                float4 v = *(float4*)&sOut[o*132+n4];
                *(float4*)&g_off[o*PLANE + base + n4] = v;
            }
        }
    }
}

// ==================== deformable conv + residual + lrelu ====================
// smem: misc[0,1024) | SA0@1024 SA1@17408 SB0@33792 SB1@41984 |
//       sOff@50176 (ushort4 x 3456 = 27648) | sWt@77824 (uint2 x 3456 = 27648) end 105472
#define SMEM_DEF 105472

__device__ __forceinline__ void dledg(int tap, int tid, const ushort4* sOff, const uint2* sWt,
                                      uint4 P[2][4], uint2 Wp[2], int j0){
    int oc = tid&7;
    #pragma unroll
    for (int jj=0;jj<2;jj++){
        int n = (tid>>3) + (j0+jj)*32;
        int te = tap*128 + n;
        ushort4 of = sOff[te];
        Wp[jj] = sWt[te];
        P[jj][0] = *(const uint4*)&g_y1h[(int)of.x*64 + oc*8];
        P[jj][1] = *(const uint4*)&g_y1h[(int)of.y*64 + oc*8];
        P[jj][2] = *(const uint4*)&g_y1h[(int)of.z*64 + oc*8];
        P[jj][3] = *(const uint4*)&g_y1h[(int)of.w*64 + oc*8];
    }
}
__device__ __forceinline__ void rledg(int tid, int base_p, uint4 P[2][4], uint2 Wp[2], int j0){
    int oc = tid&7;
    __half2 one0 = __floats2half2_rn(1.f, 0.f);
    __half2 zero = __floats2half2_rn(0.f, 0.f);
    uint2 w; w.x = *(uint32_t*)&one0; w.y = *(uint32_t*)&zero;
    #pragma unroll
    for (int jj=0;jj<2;jj++){
        int n = (tid>>3) + (j0+jj)*32;
        P[jj][0] = *(const uint4*)&g_xh[(base_p+n)*64 + oc*8];
        P[jj][1] = make_uint4(0,0,0,0);
        P[jj][2] = make_uint4(0,0,0,0);
        P[jj][3] = make_uint4(0,0,0,0);
        Wp[jj] = w;
    }
}
__device__ __forceinline__ void dlsts(char* SA, int tid, uint4 P[2][4], uint2 Wp[2], int j0){
    int oc = tid&7;
    #pragma unroll
    for (int jj=0;jj<2;jj++){
        int n = (tid>>3) + (j0+jj)*32;
        uint4 r = bilinH(P[jj], Wp[jj]);
        *(uint4*)(SA + n*128 + ((oc ^ (n&7))<<4)) = r;
    }
}

__global__ void __launch_bounds__(256)
deform_f16(const float* __restrict__ bd, const float* __restrict__ br,
           float* __restrict__ out)
{
    extern __shared__ char sm[];
    float* sBd = (float*)sm;
    float* sBr = (float*)(sm + 256);
    char* SA0 = sm + 1024;
    char* SA1 = sm + 17408;
    char* SB0 = sm + 33792;
    char* SB1 = sm + 41984;
    ushort4* sOff = (ushort4*)(sm + 50176);
    uint2*   sWt  = (uint2*)(sm + 77824);
    uint32_t sbase = smem_u32(sm);

    int tid = threadIdx.x, lane = tid&31, wid = tid>>5;
    int t = blockIdx.x>>5, h0 = (blockIdx.x&31)<<1;
    if (tid < 64){ sBd[tid] = bd[tid]; sBr[tid] = br[tid]; }

    // tap table: fully resolved offsets (clamped) + pre-masked weights (half2 x2)
    for (int e = tid; e < KTAP*128; e += 256){
        int tap = e>>7, n = e&127;
        int hh = n>>6, w = n&63;
        int h = h0 + hh;
        int kt = tap/9, rr = tap-kt*9, kh = rr/3, kw = rr-kh*3;
        int t_in = t-1+kt;
        bool t_ok = (unsigned)t_in < TT;
        int t_c = min(max(t_in,0),TT-1);
        int pidx = t*HWX + h*WWD + w;
        float dh = g_off[(2*tap)*PLANE + pidx];
        float dw = g_off[(2*tap+1)*PLANE + pidx];
        float h_s = (float)(h-1+kh)+dh, w_s = (float)(w-1+kw)+dw;
        float h0f = floorf(h_s), w0f = floorf(w_s);
        float fh = h_s-h0f, fw = w_s-w0f;
        int hb = (int)h0f, wb = (int)w0f;
        float wgt[4];
        unsigned short ofs[4];
        int tb = t_c*HWX;
        #pragma unroll
        for (int qq = 0; qq < 4; qq++){
            int ih = hb + (qq>>1), iw = wb + (qq&1);
            bool ok = t_ok && ((unsigned)ih < HH) && ((unsigned)iw < WWD);
            int ihc = min(max(ih,0),HH-1), iwc = min(max(iw,0),WWD-1);
            float whv = (qq>>1) ? fh : 1.f - fh;
            float wvv = (qq&1)  ? fw : 1.f - fw;
            wgt[qq] = ok ? whv*wvv : 0.f;
            ofs[qq] = (unsigned short)(tb + ihc*WWD + iwc);
        }
        sOff[e] = make_ushort4(ofs[0], ofs[1], ofs[2], ofs[3]);
        __half2 w01 = __floats2half2_rn(wgt[0], wgt[1]);
        __half2 w23 = __floats2half2_rn(wgt[2], wgt[3]);
        uint2 wp; wp.x = *(uint32_t*)&w01; wp.y = *(uint32_t*)&w23;
        sWt[e] = wp;
    }
    __syncthreads();

    int m0 = (wid&3)*32, n0 = (wid>>2)*32;
    int base_p = t*HWX + h0*WWD;
    float acc[8][4];
    #pragma unroll
    for (int i=0;i<8;i++){ acc[i][0]=0.f; acc[i][1]=0.f; acc[i][2]=0.f; acc[i][3]=0.f; }

    int o_w = tid>>2, part = tid&3, s0w = part*2;

    // prologue: stage chunk 0
    {
        uint4 P[2][4]; uint2 Wp[2];
        dledg(0, tid, sOff, sWt, P, Wp, 0); dlsts(SA0, tid, P, Wp, 0);
        dledg(0, tid, sOff, sWt, P, Wp, 2); dlsts(SA0, tid, P, Wp, 2);
        const uint4* sp = (const uint4*)(g_Wdh + o_w*64 + part*16);
        uint4 wv0 = sp[0], wv1 = sp[1];
        *(uint4*)(SB0 + o_w*128 + ((s0w ^ (o_w&7))<<4)) = wv0;
        *(uint4*)(SB0 + o_w*128 + (((s0w+1)^(o_w&7))<<4)) = wv1;
    }
    __syncthreads();

    int q = lane>>2, c2 = (lane&3)<<1;
    for (int it = 0; it < 28; it++){
        int p = it & 1;
        uint32_t Ab = sbase + (p ? 17408 : 1024);
        uint32_t Bb = sbase + (p ? 41984 : 33792);
        char* SAn = p ? SA0 : SA1;
        char* SBn = p ? SB0 : SB1;
        int nxt = it + 1;
        bool more = nxt < 28;

        uint4 P[2][4]; uint2 Wp[2];
        uint4 wv0, wv1;
        if (more){
            if (nxt < 27) dledg(nxt, tid, sOff, sWt, P, Wp, 0);
            else          rledg(tid, base_p, P, Wp, 0);
            const __half* Wsrc = (nxt < 27) ? (g_Wdh + nxt*4096) : g_Wrh;
            const uint4* sp = (const uint4*)(Wsrc + o_w*64 + part*16);
            wv0 = sp[0]; wv1 = sp[1];
        }
        gemm_half<0>(Ab, Bb, m0, n0, lane, acc);
        if (more){
            dlsts(SAn, tid, P, Wp, 0);
            if (nxt < 27) dledg(nxt, tid, sOff, sWt, P, Wp, 2);
            else          rledg(tid, base_p, P, Wp, 2);
        }
        gemm_half<2>(Ab, Bb, m0, n0, lane, acc);
        if (more){
            dlsts(SAn, tid, P, Wp, 2);
            *(uint4*)(SBn + o_w*128 + ((s0w ^ (o_w&7))<<4)) = wv0;
            *(uint4*)(SBn + o_w*128 + (((s0w+1)^(o_w&7))<<4)) = wv1;
        }
        if (it == 26){
            #pragma unroll
            for (int t8=0;t8<8;t8++){
                int ni=(t8>>1)&1, hn=t8&1;
                int o = n0 + ni*16 + hn*8 + c2;
                float b0v = sBd[o], b1v = sBd[o+1];
                float v;
                v = acc[t8][0]+b0v; acc[t8][0] = v>=0.f?v:0.01f*v;
                v = acc[t8][1]+b1v; acc[t8][1] = v>=0.f?v:0.01f*v;
                v = acc[t8][2]+b0v; acc[t8][2] = v>=0.f?v:0.01f*v;
                v = acc[t8][3]+b1v; acc[t8][3] = v>=0.f?v:0.01f*v;
            }
        }
        __syncthreads();
    }

    float* sOut = (float*)(sm + 1024);  // [o][132]
    #pragma unroll
    for (int t8=0;t8<8;t8++){
        int mi=t8>>2, ni=(t8>>1)&1, hn=t8&1;
        int o = n0 + ni*16 + hn*8 + c2;
        int nn = m0 + mi*16 + q;
        float b0v = sBr[o], b1v = sBr[o+1];
        sOut[o*132+nn]       = acc[t8][0]+b0v;
        sOut[(o+1)*132+nn]   = acc[t8][1]+b1v;
        sOut[o*132+nn+8]     = acc[t8][2]+b0v;
        sOut[(o+1)*132+nn+8] = acc[t8][3]+b1v;
    }
    __syncthreads();
    int n4 = (tid&31)*4;
    #pragma unroll
    for (int i=0;i<8;i++){
        int o = (tid>>5) + i*8;
        float4 v = *(float4*)&sOut[o*132+n4];
        *(float4*)&out[o*PLANE + base_p + n4] = v;
    }
}

// -------- launch --------
extern "C" void kernel_launch(void* const* d_in, const int* in_sizes, int n_in,
                              void* d_out, int out_size) {
    (void)in_sizes; (void)n_in; (void)out_size;
    const float* x    = (const float*)d_in[0];
    const float* W1   = (const float*)d_in[1];
    const float* b1   = (const float*)d_in[2];
    const float* Woff = (const float*)d_in[3];
    const float* boff = (const float*)d_in[4];
    const float* Wd   = (const float*)d_in[5];
    const float* bd   = (const float*)d_in[6];
    const float* Wr   = (const float*)d_in[7];
    const float* br   = (const float*)d_in[8];
    float* out = (float*)d_out;

    cudaFuncSetAttribute(conv_f16<0>, cudaFuncAttributeMaxDynamicSharedMemorySize, SMEM_CONV);
    cudaFuncSetAttribute(conv_f16<1>, cudaFuncAttributeMaxDynamicSharedMemorySize, SMEM_CONV);
    cudaFuncSetAttribute(deform_f16,  cudaFuncAttributeMaxDynamicSharedMemorySize, SMEM_DEF);

    prep_all<<<688, 256>>>(W1, Woff, Wd, Wr, x);
    conv_f16<0><<<256, 256, SMEM_CONV>>>(b1);
    conv_f16<1><<<256, 256, SMEM_CONV>>>(boff);
    deform_f16<<<256, 256, SMEM_DEF>>>(bd, br, out);
}